// round 12
// baseline (speedup 1.0000x reference)
#include <cuda_runtime.h>
#include <cuda_bf16.h>
#include <math.h>
#include <stdint.h>

// ---------------- Problem constants ----------------
#define V_SZ 50257
#define E_SZ 768
#define H_SZ 12
#define L_SZ 6
#define T_SZ 1024
#define B_SZ 2
#define D_SZ 64
#define BT   (B_SZ * T_SZ)      // 2048
#define FF   (4 * E_SZ)         // 3072
#define QKV_LD (3 * E_SZ)       // 2304

// ---------------- Scratch (device globals; no allocations allowed) ----------
__device__ float g_x   [BT * E_SZ];
__device__ float g_h   [BT * E_SZ];
__device__ float g_qkv [BT * QKV_LD];
__device__ float g_att [BT * E_SZ];
__device__ float g_m1  [BT * FF];
// tf32-rounded weight copies
__device__ float g_wqkv[L_SZ * E_SZ * QKV_LD];
__device__ float g_wo  [L_SZ * E_SZ * E_SZ];
__device__ float g_w1  [L_SZ * E_SZ * FF];
__device__ float g_w2  [L_SZ * E_SZ * FF];
__device__ float g_wte [V_SZ * E_SZ];

// ---------------- tf32 helpers ----------------
__device__ __forceinline__ unsigned f2tf(float f) {
    unsigned u;
    asm("cvt.rna.tf32.f32 %0, %1;" : "=r"(u) : "f"(f));
    return u;
}
__device__ __forceinline__ float rtf(float f) { return __uint_as_float(f2tf(f)); }
__device__ __forceinline__ float4 rtf4(float4 v) {
    v.x = rtf(v.x); v.y = rtf(v.y); v.z = rtf(v.z); v.w = rtf(v.w);
    return v;
}

__global__ void cvt_kernel(const float4* __restrict__ src, float4* __restrict__ dst, int n4) {
    int i = blockIdx.x * 256 + threadIdx.x;
    if (i < n4) dst[i] = rtf4(src[i]);
}

__global__ void pack_qkv_kernel(const float4* __restrict__ q, const float4* __restrict__ k,
                                const float4* __restrict__ v, float4* __restrict__ dst, int n4) {
    int i = blockIdx.x * 256 + threadIdx.x;
    if (i >= n4) return;
    const int per = E_SZ * E_SZ / 4;
    const int rw  = E_SZ / 4;
    int l = i / per, r = i % per;
    int row = r / rw, c4 = r % rw;
    size_t base = (size_t)l * (E_SZ * QKV_LD / 4) + (size_t)row * (QKV_LD / 4) + c4;
    dst[base]          = rtf4(q[i]);
    dst[base + rw]     = rtf4(k[i]);
    dst[base + 2 * rw] = rtf4(v[i]);
}

// ---------------- Embedding ----------------
__global__ void embed_kernel(const int* __restrict__ tok,
                             const float* __restrict__ wte,
                             const float* __restrict__ wpe,
                             float* __restrict__ x) {
    int row = blockIdx.x;
    int t   = row % T_SZ;
    int tk  = tok[row];
    int e   = threadIdx.x * 4;
    const float4 a = *(const float4*)(wte + (size_t)tk * E_SZ + e);
    const float4 b = *(const float4*)(wpe + (size_t)t  * E_SZ + e);
    float4 o;
    o.x = a.x + b.x; o.y = a.y + b.y; o.z = a.z + b.z; o.w = a.w + b.w;
    *(float4*)(x + (size_t)row * E_SZ + e) = o;
}

// ---------------- LayerNorm (emits tf32-rounded output) ----------------
__global__ void layernorm_kernel(const float* __restrict__ x,
                                 const float* __restrict__ sc,
                                 const float* __restrict__ bi,
                                 float* __restrict__ out) {
    int row = blockIdx.x;
    const float* xr = x + (size_t)row * E_SZ;
    float lv[3];
    float s = 0.f, sq = 0.f;
#pragma unroll
    for (int i = 0; i < 3; i++) {
        float t = xr[threadIdx.x + i * 256];
        lv[i] = t; s += t; sq += t * t;
    }
#pragma unroll
    for (int o = 16; o > 0; o >>= 1) {
        s  += __shfl_down_sync(0xffffffffu, s,  o);
        sq += __shfl_down_sync(0xffffffffu, sq, o);
    }
    __shared__ float sa[8], sb[8];
    int w = threadIdx.x >> 5, lane = threadIdx.x & 31;
    if (lane == 0) { sa[w] = s; sb[w] = sq; }
    __syncthreads();
    __shared__ float s_mu, s_rstd;
    if (threadIdx.x == 0) {
        float ts = 0.f, tq = 0.f;
#pragma unroll
        for (int i = 0; i < 8; i++) { ts += sa[i]; tq += sb[i]; }
        float mu  = ts * (1.0f / E_SZ);
        float var = tq * (1.0f / E_SZ) - mu * mu;
        s_mu = mu;
        s_rstd = rsqrtf(var + 1e-5f);
    }
    __syncthreads();
    float mu = s_mu, rstd = s_rstd;
#pragma unroll
    for (int i = 0; i < 3; i++) {
        int c = threadIdx.x + i * 256;
        out[(size_t)row * E_SZ + c] = rtf((lv[i] - mu) * rstd * sc[c] + bi[c]);
    }
}

// ---------------- cp.async helpers ----------------
__device__ __forceinline__ void cp16(unsigned sdst, const void* src, bool pred) {
    int sz = pred ? 16 : 0;
    asm volatile("cp.async.cg.shared.global [%0], [%1], 16, %2;\n"
                 :: "r"(sdst), "l"(src), "r"(sz));
}
__device__ __forceinline__ void cp_commit() {
    asm volatile("cp.async.commit_group;\n");
}
__device__ __forceinline__ void cp_wait1() {
    asm volatile("cp.async.wait_group 1;\n");
}

// ---------------- TF32 mma.sync GEMM (layer GEMMs) ----------------
__device__ __forceinline__ float gelu_exact(float v) {
    return 0.5f * v * (1.0f + erff(v * 0.70710678118654752f));
}
__device__ __forceinline__ void mma_tf32(float* d, const unsigned* a, const unsigned* b) {
    asm volatile(
        "mma.sync.aligned.m16n8k8.row.col.f32.tf32.tf32.f32 "
        "{%0,%1,%2,%3}, {%4,%5,%6,%7}, {%8,%9}, {%0,%1,%2,%3};"
        : "+f"(d[0]), "+f"(d[1]), "+f"(d[2]), "+f"(d[3])
        : "r"(a[0]), "r"(a[1]), "r"(a[2]), "r"(a[3]), "r"(b[0]), "r"(b[1]));
}

template <int BN, int EPI>
__device__ __forceinline__
void tgemm_dev(const float* __restrict__ A, const float* __restrict__ Bm,
               const float* __restrict__ bias, const float* __restrict__ resid,
               float* __restrict__ C, int N, int K, int bm, int bn) {
    constexpr int BK   = 16;
    constexpr int NJ   = BN / 16;
    constexpr int BROW = BN + 4;
    constexpr int ASZ  = 128 * 20;
    constexpr int BSZ  = BK * BROW;

    extern __shared__ unsigned smem_u[];
    unsigned* sA = smem_u;
    unsigned* sB = smem_u + 3 * ASZ;

    const int tid  = threadIdx.x;
    const int lane = tid & 31;
    const int wid  = tid >> 5;
    const int wm   = (wid & 3) * 32;
    const int wn   = (wid >> 2) * (BN / 2);
    const int g    = lane >> 2;
    const int t    = lane & 3;

    float acc[2][NJ][4];
#pragma unroll
    for (int i = 0; i < 2; i++)
#pragma unroll
        for (int j = 0; j < NJ; j++)
#pragma unroll
            for (int r = 0; r < 4; r++) acc[i][j][r] = 0.f;

    const int ar = tid >> 2;
    const int ak = (tid & 3) * 4;
    const int nbR = (BN == 128) ? (tid >> 5) : (tid >> 4);
    const int nbC = (BN == 128) ? ((tid & 31) * 4) : ((tid & 15) * 4);

    const unsigned sAaddr = (unsigned)__cvta_generic_to_shared(sA);
    const unsigned sBaddr = (unsigned)__cvta_generic_to_shared(sB);

    const int ntiles = K / BK;

    auto issue = [&](int st, int kt) {
        const int k0 = kt * BK;
        unsigned a_s = sAaddr + (st * ASZ) * 4;
        unsigned b_s = sBaddr + (st * BSZ) * 4;
        const float* ap = A + (size_t)(bm + ar) * K + k0 + ak;
        cp16(a_s + (ar * 20 + ak) * 4,        ap,                  true);
        cp16(a_s + ((ar + 64) * 20 + ak) * 4, ap + (size_t)64 * K, true);
        const float* bp = Bm + (size_t)(k0 + nbR) * N + bn + nbC;
        cp16(b_s + (nbR * BROW + nbC) * 4, bp, true);
        if (BN == 128)
            cp16(b_s + ((nbR + 8) * BROW + nbC) * 4, bp + (size_t)8 * N, true);
    };

    issue(0, 0); cp_commit();
    issue(1, 1); cp_commit();

    for (int kt = 0; kt < ntiles; kt++) {
        cp_wait1();
        __syncthreads();
        const int cur = kt % 3;
        const unsigned* As = sA + cur * ASZ;
        const unsigned* Bs = sB + cur * BSZ;
#pragma unroll
        for (int ks = 0; ks < 2; ks++) {
            const int k8 = ks * 8;
            unsigned af[2][4], bf[NJ][2];
#pragma unroll
            for (int i = 0; i < 2; i++) {
                const int mr = wm + i * 16 + g;
                af[i][0] = As[mr * 20 + k8 + t];
                af[i][1] = As[(mr + 8) * 20 + k8 + t];
                af[i][2] = As[mr * 20 + k8 + t + 4];
                af[i][3] = As[(mr + 8) * 20 + k8 + t + 4];
            }
#pragma unroll
            for (int j = 0; j < NJ; j++) {
                const int nc = wn + j * 8 + g;
                bf[j][0] = Bs[(k8 + t) * BROW + nc];
                bf[j][1] = Bs[(k8 + t + 4) * BROW + nc];
            }
#pragma unroll
            for (int i = 0; i < 2; i++)
#pragma unroll
                for (int j = 0; j < NJ; j++)
                    mma_tf32(acc[i][j], af[i], bf[j]);
        }
        if (kt + 2 < ntiles) issue((kt + 2) % 3, kt + 2);
        cp_commit();
    }

#pragma unroll
    for (int i = 0; i < 2; i++) {
        const int r0 = bm + wm + i * 16 + g;
        const int r1 = r0 + 8;
#pragma unroll
        for (int j = 0; j < NJ; j++) {
            const int c = bn + wn + j * 8 + 2 * t;
            float v00 = acc[i][j][0], v01 = acc[i][j][1];
            float v10 = acc[i][j][2], v11 = acc[i][j][3];
            if (EPI & 1) {
                float bb0 = bias[c], bb1 = bias[c + 1];
                v00 += bb0; v01 += bb1; v10 += bb0; v11 += bb1;
            }
            if (EPI & 2) {
                v00 = gelu_exact(v00); v01 = gelu_exact(v01);
                v10 = gelu_exact(v10); v11 = gelu_exact(v11);
            }
            if (EPI & 4) {
                const float* rp0 = resid + (size_t)r0 * N + c;
                const float* rp1 = resid + (size_t)r1 * N + c;
                v00 += rp0[0]; v01 += rp0[1];
                v10 += rp1[0]; v11 += rp1[1];
            }
            if (EPI & 8) {
                v00 = rtf(v00); v01 = rtf(v01);
                v10 = rtf(v10); v11 = rtf(v11);
            }
            float2 p0; p0.x = v00; p0.y = v01;
            float2 p1; p1.x = v10; p1.y = v11;
            *(float2*)(C + (size_t)r0 * N + c) = p0;
            *(float2*)(C + (size_t)r1 * N + c) = p1;
        }
    }
}

template <int BN, int EPI>
__global__ __launch_bounds__(256)
void tgemm_k(const float* __restrict__ A, const float* __restrict__ Bm,
             const float* __restrict__ bias, const float* __restrict__ resid,
             float* __restrict__ C, int N, int K) {
    tgemm_dev<BN, EPI>(A, Bm, bias, resid, C, N, K,
                       blockIdx.x * 128, blockIdx.y * BN);
}

#define SM_G64F  (3 * (128 * 20 + 16 * 68) * 4)    // 43776
#define SM_G128F (3 * (128 * 20 + 16 * 132) * 4)   // 56064

// ---------------- Logits GEMM: BM=256, BN=128, 512 threads, TRANSB --------
// D[2048, V] = h @ wte^T.  16 warps: 8(m) x 2(n); warp tile 32 x 64.
// 3-stage cp.async; B-tile L2 traffic halved vs BM=128.
#define SM_LOG (3 * (256 * 20 + 128 * 20) * 4)     // 92160

__global__ __launch_bounds__(512)
void logits_k(const float* __restrict__ A, const float* __restrict__ Bm,
              float* __restrict__ C, int N, int K) {
    constexpr int BK  = 16;
    constexpr int ASZ = 256 * 20;
    constexpr int BSZ = 128 * 20;

    extern __shared__ unsigned smem_u[];
    unsigned* sA = smem_u;
    unsigned* sB = smem_u + 3 * ASZ;

    const int bm  = blockIdx.x * 256;
    const int bn  = blockIdx.y * 128;
    const int tid = threadIdx.x;
    const int lane = tid & 31;
    const int wid  = tid >> 5;
    const int wm   = (wid & 7) * 32;       // 8 m-warps
    const int wn   = (wid >> 3) * 64;      // 2 n-warps
    const int g    = lane >> 2;
    const int t    = lane & 3;

    float acc[2][8][4];
#pragma unroll
    for (int i = 0; i < 2; i++)
#pragma unroll
        for (int j = 0; j < 8; j++)
#pragma unroll
            for (int r = 0; r < 4; r++) acc[i][j][r] = 0.f;

    // staging: A 256x16 (1024 f4, 2/thread); B 128x16 n-major (512 f4, 1/thread)
    const int ar  = tid >> 1;              // 0..255
    const int ak  = (tid & 1) * 8;         // 0 or 8 (two f4 each)
    const int tbN = tid >> 2;              // 0..127
    const int tbK = (tid & 3) * 4;

    const unsigned sAaddr = (unsigned)__cvta_generic_to_shared(sA);
    const unsigned sBaddr = (unsigned)__cvta_generic_to_shared(sB);

    const int ntiles = K / BK;             // 48

    auto issue = [&](int st, int kt) {
        const int k0 = kt * BK;
        unsigned a_s = sAaddr + (st * ASZ) * 4;
        unsigned b_s = sBaddr + (st * BSZ) * 4;
        const float* ap = A + (size_t)(bm + ar) * K + k0 + ak;
        cp16(a_s + (ar * 20 + ak) * 4,     ap,     true);
        cp16(a_s + (ar * 20 + ak + 4) * 4, ap + 4, true);
        int gn = bn + tbN;
        const float* bp = Bm + (size_t)(gn < N ? gn : 0) * K + k0 + tbK;
        cp16(b_s + (tbN * 20 + tbK) * 4, bp, gn < N);
    };

    issue(0, 0); cp_commit();
    issue(1, 1); cp_commit();

    for (int kt = 0; kt < ntiles; kt++) {
        cp_wait1();
        __syncthreads();
        const int cur = kt % 3;
        const unsigned* As = sA + cur * ASZ;
        const unsigned* Bs = sB + cur * BSZ;
#pragma unroll
        for (int ks = 0; ks < 2; ks++) {
            const int k8 = ks * 8;
            unsigned af[2][4], bf[8][2];
#pragma unroll
            for (int i = 0; i < 2; i++) {
                const int mr = wm + i * 16 + g;
                af[i][0] = As[mr * 20 + k8 + t];
                af[i][1] = As[(mr + 8) * 20 + k8 + t];
                af[i][2] = As[mr * 20 + k8 + t + 4];
                af[i][3] = As[(mr + 8) * 20 + k8 + t + 4];
            }
#pragma unroll
            for (int j = 0; j < 8; j++) {
                const int nc = wn + j * 8 + g;
                bf[j][0] = Bs[nc * 20 + k8 + t];
                bf[j][1] = Bs[nc * 20 + k8 + t + 4];
            }
#pragma unroll
            for (int i = 0; i < 2; i++)
#pragma unroll
                for (int j = 0; j < 8; j++)
                    mma_tf32(acc[i][j], af[i], bf[j]);
        }
        if (kt + 2 < ntiles) issue((kt + 2) % 3, kt + 2);
        cp_commit();
    }

    // epilogue: scalar bounds-checked stores (V odd)
#pragma unroll
    for (int i = 0; i < 2; i++) {
        const int r0 = bm + wm + i * 16 + g;
        const int r1 = r0 + 8;
        float* cp0 = C + (size_t)r0 * N;
        float* cp1 = C + (size_t)r1 * N;
#pragma unroll
        for (int j = 0; j < 8; j++) {
            const int c = bn + wn + j * 8 + 2 * t;
            if (c < N)     { cp0[c]     = acc[i][j][0]; cp1[c]     = acc[i][j][2]; }
            if (c + 1 < N) { cp0[c + 1] = acc[i][j][1]; cp1[c + 1] = acc[i][j][3]; }
        }
    }
}

// ---------------- Causal attention: 64q flash tile ----------------
#define ATTN_SMEM (4 * 64 * 68 * 4 + 2 * 64 * 4)

__global__ __launch_bounds__(256)
void attn_kernel(const float* __restrict__ qkv, float* __restrict__ o) {
    extern __shared__ float sm[];
    float (*Qs)[68] = (float(*)[68])sm;
    float (*Ks)[68] = (float(*)[68])(sm + 64 * 68);
    float (*Vs)[68] = (float(*)[68])(sm + 2 * 64 * 68);
    float (*Ss)[68] = (float(*)[68])(sm + 3 * 64 * 68);
    float* ms = sm + 4 * 64 * 68;
    float* ls = ms + 64;

    const int bh  = blockIdx.y;
    const int b   = bh / H_SZ, h = bh % H_SZ;
    const int q0  = blockIdx.x * 64;
    const int tid = threadIdx.x;
    const int tx  = tid & 15, ty = tid >> 4;

    const float* qb = qkv + h * D_SZ;
    const float* kb = qkv + E_SZ + h * D_SZ;
    const float* vb = qkv + 2 * E_SZ + h * D_SZ;

#pragma unroll
    for (int i = 0; i < 4; i++) {
        int f  = tid + i * 256;
        int qq = f & 63, d4 = (f >> 6) * 4;
        float4 t = *(const float4*)(qb + (size_t)(b * T_SZ + q0 + qq) * QKV_LD + d4);
        Qs[d4+0][qq] = t.x * 0.125f; Qs[d4+1][qq] = t.y * 0.125f;
        Qs[d4+2][qq] = t.z * 0.125f; Qs[d4+3][qq] = t.w * 0.125f;
    }
    if (tid < 64) { ms[tid] = -1e30f; ls[tid] = 0.f; }

    float acc[4][4];
#pragma unroll
    for (int r = 0; r < 4; r++)
#pragma unroll
        for (int c = 0; c < 4; c++) acc[r][c] = 0.f;

    for (int kt = 0; kt <= q0; kt += 64) {
#pragma unroll
        for (int i = 0; i < 4; i++) {
            int f  = tid + i * 256;
            int kk = f & 63, d4 = (f >> 6) * 4;
            float4 t = *(const float4*)(kb + (size_t)(b * T_SZ + kt + kk) * QKV_LD + d4);
            Ks[d4+0][kk] = t.x; Ks[d4+1][kk] = t.y;
            Ks[d4+2][kk] = t.z; Ks[d4+3][kk] = t.w;
        }
#pragma unroll
        for (int i = 0; i < 4; i++) {
            int f  = tid + i * 256;
            int kk = f >> 4, d4 = (f & 15) * 4;
            *(float4*)&Vs[kk][d4] =
                *(const float4*)(vb + (size_t)(b * T_SZ + kt + kk) * QKV_LD + d4);
        }
        __syncthreads();

        float s[4][4];
#pragma unroll
        for (int r = 0; r < 4; r++)
#pragma unroll
            for (int c = 0; c < 4; c++) s[r][c] = 0.f;
#pragma unroll 4
        for (int d = 0; d < 64; d++) {
            float4 aq = *(const float4*)&Qs[d][4 * ty];
            float4 bk = *(const float4*)&Ks[d][4 * tx];
            float a[4] = {aq.x, aq.y, aq.z, aq.w};
            float bb[4] = {bk.x, bk.y, bk.z, bk.w};
#pragma unroll
            for (int r = 0; r < 4; r++)
#pragma unroll
                for (int c = 0; c < 4; c++) s[r][c] += a[r] * bb[c];
        }

        const bool diag = (kt == q0);
        float cfl[4];
#pragma unroll
        for (int r = 0; r < 4; r++) {
            const int row = 4 * ty + r;
            if (diag) {
#pragma unroll
                for (int c = 0; c < 4; c++)
                    if (4 * tx + c > row) s[r][c] = -1e30f;
            }
            float mx = fmaxf(fmaxf(s[r][0], s[r][1]), fmaxf(s[r][2], s[r][3]));
#pragma unroll
            for (int off = 1; off < 16; off <<= 1)
                mx = fmaxf(mx, __shfl_xor_sync(0xffffffffu, mx, off));
            const float mold = ms[row];
            const float mnew = fmaxf(mold, mx);
            float ps = 0.f;
#pragma unroll
            for (int c = 0; c < 4; c++) {
                float p = __expf(s[r][c] - mnew);
                Ss[row][4 * tx + c] = p;
                ps += p;
            }
#pragma unroll
            for (int off = 1; off < 16; off <<= 1)
                ps += __shfl_xor_sync(0xffffffffu, ps, off);
            cfl[r] = __expf(mold - mnew);
            if (tx == 0) { ms[row] = mnew; ls[row] = ls[row] * cfl[r] + ps; }
        }
        __syncwarp();

#pragma unroll
        for (int r = 0; r < 4; r++)
#pragma unroll
            for (int c = 0; c < 4; c++) acc[r][c] *= cfl[r];
#pragma unroll 4
        for (int kk = 0; kk < 64; kk++) {
            float4 vv = *(const float4*)&Vs[kk][4 * tx];
#pragma unroll
            for (int r = 0; r < 4; r++) {
                float p = Ss[4 * ty + r][kk];
                acc[r][0] += p * vv.x; acc[r][1] += p * vv.y;
                acc[r][2] += p * vv.z; acc[r][3] += p * vv.w;
            }
        }
        __syncthreads();
    }

#pragma unroll
    for (int r = 0; r < 4; r++) {
        const float inv = 1.f / ls[4 * ty + r];
        float4 t;
        t.x = rtf(acc[r][0] * inv); t.y = rtf(acc[r][1] * inv);
        t.z = rtf(acc[r][2] * inv); t.w = rtf(acc[r][3] * inv);
        *(float4*)(o + (size_t)(b * T_SZ + q0 + 4 * ty + r) * E_SZ + h * D_SZ + 4 * tx) = t;
    }
}

// ---------------- Host orchestration ----------------
extern "C" void kernel_launch(void* const* d_in, const int* in_sizes, int n_in,
                              void* d_out, int out_size) {
    (void)in_sizes; (void)n_in; (void)out_size;
    const int*   tokens = (const int*)  d_in[0];
    const float* wte    = (const float*)d_in[1];
    const float* wpe    = (const float*)d_in[2];
    const float* Wq     = (const float*)d_in[3];
    const float* Wk     = (const float*)d_in[4];
    const float* Wv     = (const float*)d_in[5];
    const float* Wo     = (const float*)d_in[6];
    const float* bo     = (const float*)d_in[7];
    const float* ln1_s  = (const float*)d_in[8];
    const float* ln1_b  = (const float*)d_in[9];
    const float* W1     = (const float*)d_in[10];
    const float* b1     = (const float*)d_in[11];
    const float* W2     = (const float*)d_in[12];
    const float* b2     = (const float*)d_in[13];
    const float* ln2_s  = (const float*)d_in[14];
    const float* ln2_b  = (const float*)d_in[15];
    const float* lnf_s  = (const float*)d_in[16];
    const float* lnf_b  = (const float*)d_in[17];
    float* out = (float*)d_out;

    float *x, *h, *qkv, *att, *m1;
    float *wqkv, *wo, *w1, *w2, *wt;
    cudaGetSymbolAddress((void**)&x,    g_x);
    cudaGetSymbolAddress((void**)&h,    g_h);
    cudaGetSymbolAddress((void**)&qkv,  g_qkv);
    cudaGetSymbolAddress((void**)&att,  g_att);
    cudaGetSymbolAddress((void**)&m1,   g_m1);
    cudaGetSymbolAddress((void**)&wqkv, g_wqkv);
    cudaGetSymbolAddress((void**)&wo,   g_wo);
    cudaGetSymbolAddress((void**)&w1,   g_w1);
    cudaGetSymbolAddress((void**)&w2,   g_w2);
    cudaGetSymbolAddress((void**)&wt,   g_wte);

    cudaFuncSetAttribute(attn_kernel,
                         cudaFuncAttributeMaxDynamicSharedMemorySize, ATTN_SMEM);
    cudaFuncSetAttribute(tgemm_k<64, 5>,
                         cudaFuncAttributeMaxDynamicSharedMemorySize, SM_G64F);
    cudaFuncSetAttribute(tgemm_k<128, 0>,
                         cudaFuncAttributeMaxDynamicSharedMemorySize, SM_G128F);
    cudaFuncSetAttribute(tgemm_k<128, 11>,
                         cudaFuncAttributeMaxDynamicSharedMemorySize, SM_G128F);
    cudaFuncSetAttribute(logits_k,
                         cudaFuncAttributeMaxDynamicSharedMemorySize, SM_LOG);

    // ---- per-launch weight rounding / packing ----
    {
        const int nE = L_SZ * E_SZ * E_SZ / 4;
        const int nF = L_SZ * E_SZ * FF / 4;
        const int nV = V_SZ * E_SZ / 4;
        pack_qkv_kernel<<<(nE + 255) / 256, 256>>>(
            (const float4*)Wq, (const float4*)Wk, (const float4*)Wv, (float4*)wqkv, nE);
        cvt_kernel<<<(nE + 255) / 256, 256>>>((const float4*)Wo, (float4*)wo, nE);
        cvt_kernel<<<(nF + 255) / 256, 256>>>((const float4*)W1, (float4*)w1, nF);
        cvt_kernel<<<(nF + 255) / 256, 256>>>((const float4*)W2, (float4*)w2, nF);
        cvt_kernel<<<(nV + 255) / 256, 256>>>((const float4*)wte, (float4*)wt, nV);
    }

    embed_kernel<<<BT, 192>>>(tokens, wte, wpe, x);

    const dim3 gE(BT / 128, E_SZ / 64);            // 16 x 12
    const dim3 gQKV(BT / 128, QKV_LD / 128);       // 16 x 18
    const dim3 gF(BT / 128, FF / 128);             // 16 x 24
    const dim3 gATT(T_SZ / 64, B_SZ * H_SZ);       // 16 x 24
    const dim3 gLOG(BT / 256, (V_SZ + 127) / 128); // 8 x 393

    for (int l = 0; l < L_SZ; l++) {
        const size_t wqOff = (size_t)l * E_SZ * QKV_LD;
        const size_t wOff  = (size_t)l * E_SZ * E_SZ;
        const size_t w1Off = (size_t)l * E_SZ * FF;
        const size_t vOff  = (size_t)l * E_SZ;
        const size_t fOff  = (size_t)l * FF;

        layernorm_kernel<<<BT, 256>>>(x, ln1_s + vOff, ln1_b + vOff, h);
        tgemm_k<128, 0><<<gQKV, 256, SM_G128F>>>(h, wqkv + wqOff, nullptr, nullptr,
                                                 qkv, QKV_LD, E_SZ);
        attn_kernel<<<gATT, 256, ATTN_SMEM>>>(qkv, att);
        tgemm_k<64, 5><<<gE, 256, SM_G64F>>>(att, wo + wOff, bo + vOff, x, x, E_SZ, E_SZ);
        layernorm_kernel<<<BT, 256>>>(x, ln2_s + vOff, ln2_b + vOff, h);
        tgemm_k<128, 11><<<gF, 256, SM_G128F>>>(h, w1 + w1Off, b1 + fOff, nullptr, m1, FF, E_SZ);
        tgemm_k<64, 5><<<gE, 256, SM_G64F>>>(m1, w2 + w1Off, b2 + vOff, x, x, E_SZ, FF);
    }

    layernorm_kernel<<<BT, 256>>>(x, lnf_s, lnf_b, h);
    logits_k<<<gLOG, 512, SM_LOG>>>(h, wt, out, V_SZ, E_SZ);
}

// round 13
// speedup vs baseline: 1.0584x; 1.0584x over previous
#include <cuda_runtime.h>
#include <cuda_bf16.h>
#include <math.h>
#include <stdint.h>

// ---------------- Problem constants ----------------
#define V_SZ 50257
#define E_SZ 768
#define H_SZ 12
#define L_SZ 6
#define T_SZ 1024
#define B_SZ 2
#define D_SZ 64
#define BT   (B_SZ * T_SZ)      // 2048
#define FF   (4 * E_SZ)         // 3072
#define QKV_LD (3 * E_SZ)       // 2304

// ---------------- Scratch ----------------
__device__ float g_x   [BT * E_SZ];
__device__ float g_h   [BT * E_SZ];
__device__ float g_qkv [BT * QKV_LD];
__device__ float g_att [BT * E_SZ];
__device__ float g_m1  [BT * FF];
__device__ float g_wqkv[L_SZ * E_SZ * QKV_LD];
__device__ float g_wo  [L_SZ * E_SZ * E_SZ];
__device__ float g_w1  [L_SZ * E_SZ * FF];
__device__ float g_w2  [L_SZ * E_SZ * FF];
__device__ float g_wte [V_SZ * E_SZ];

// ---------------- tf32 helpers ----------------
__device__ __forceinline__ unsigned f2tf(float f) {
    unsigned u;
    asm("cvt.rna.tf32.f32 %0, %1;" : "=r"(u) : "f"(f));
    return u;
}
__device__ __forceinline__ float rtf(float f) { return __uint_as_float(f2tf(f)); }
__device__ __forceinline__ float4 rtf4(float4 v) {
    v.x = rtf(v.x); v.y = rtf(v.y); v.z = rtf(v.z); v.w = rtf(v.w);
    return v;
}

__global__ void cvt_kernel(const float4* __restrict__ src, float4* __restrict__ dst, int n4) {
    int i = blockIdx.x * 256 + threadIdx.x;
    if (i < n4) dst[i] = rtf4(src[i]);
}

__global__ void pack_qkv_kernel(const float4* __restrict__ q, const float4* __restrict__ k,
                                const float4* __restrict__ v, float4* __restrict__ dst, int n4) {
    int i = blockIdx.x * 256 + threadIdx.x;
    if (i >= n4) return;
    const int per = E_SZ * E_SZ / 4;
    const int rw  = E_SZ / 4;
    int l = i / per, r = i % per;
    int row = r / rw, c4 = r % rw;
    size_t base = (size_t)l * (E_SZ * QKV_LD / 4) + (size_t)row * (QKV_LD / 4) + c4;
    dst[base]          = rtf4(q[i]);
    dst[base + rw]     = rtf4(k[i]);
    dst[base + 2 * rw] = rtf4(v[i]);
}

// ---------------- Embedding ----------------
__global__ void embed_kernel(const int* __restrict__ tok,
                             const float* __restrict__ wte,
                             const float* __restrict__ wpe,
                             float* __restrict__ x) {
    int row = blockIdx.x;
    int t   = row % T_SZ;
    int tk  = tok[row];
    int e   = threadIdx.x * 4;
    const float4 a = *(const float4*)(wte + (size_t)tk * E_SZ + e);
    const float4 b = *(const float4*)(wpe + (size_t)t  * E_SZ + e);
    float4 o;
    o.x = a.x + b.x; o.y = a.y + b.y; o.z = a.z + b.z; o.w = a.w + b.w;
    *(float4*)(x + (size_t)row * E_SZ + e) = o;
}

// ---------------- LayerNorm (tf32-rounded output) ----------------
__global__ void layernorm_kernel(const float* __restrict__ x,
                                 const float* __restrict__ sc,
                                 const float* __restrict__ bi,
                                 float* __restrict__ out) {
    int row = blockIdx.x;
    const float* xr = x + (size_t)row * E_SZ;
    float lv[3];
    float s = 0.f, sq = 0.f;
#pragma unroll
    for (int i = 0; i < 3; i++) {
        float t = xr[threadIdx.x + i * 256];
        lv[i] = t; s += t; sq += t * t;
    }
#pragma unroll
    for (int o = 16; o > 0; o >>= 1) {
        s  += __shfl_down_sync(0xffffffffu, s,  o);
        sq += __shfl_down_sync(0xffffffffu, sq, o);
    }
    __shared__ float sa[8], sb[8];
    int w = threadIdx.x >> 5, lane = threadIdx.x & 31;
    if (lane == 0) { sa[w] = s; sb[w] = sq; }
    __syncthreads();
    __shared__ float s_mu, s_rstd;
    if (threadIdx.x == 0) {
        float ts = 0.f, tq = 0.f;
#pragma unroll
        for (int i = 0; i < 8; i++) { ts += sa[i]; tq += sb[i]; }
        float mu  = ts * (1.0f / E_SZ);
        float var = tq * (1.0f / E_SZ) - mu * mu;
        s_mu = mu;
        s_rstd = rsqrtf(var + 1e-5f);
    }
    __syncthreads();
    float mu = s_mu, rstd = s_rstd;
#pragma unroll
    for (int i = 0; i < 3; i++) {
        int c = threadIdx.x + i * 256;
        out[(size_t)row * E_SZ + c] = rtf((lv[i] - mu) * rstd * sc[c] + bi[c]);
    }
}

// ---------------- cp.async helpers ----------------
__device__ __forceinline__ void cp16(unsigned sdst, const void* src, bool pred) {
    int sz = pred ? 16 : 0;
    asm volatile("cp.async.cg.shared.global [%0], [%1], 16, %2;\n"
                 :: "r"(sdst), "l"(src), "r"(sz));
}
__device__ __forceinline__ void cp_commit() {
    asm volatile("cp.async.commit_group;\n");
}
__device__ __forceinline__ void cp_wait1() {
    asm volatile("cp.async.wait_group 1;\n");
}

// ---------------- TF32 mma.sync GEMM (128-row tiles) ----------------
__device__ __forceinline__ float gelu_exact(float v) {
    return 0.5f * v * (1.0f + erff(v * 0.70710678118654752f));
}
__device__ __forceinline__ void mma_tf32(float* d, const unsigned* a, const unsigned* b) {
    asm volatile(
        "mma.sync.aligned.m16n8k8.row.col.f32.tf32.tf32.f32 "
        "{%0,%1,%2,%3}, {%4,%5,%6,%7}, {%8,%9}, {%0,%1,%2,%3};"
        : "+f"(d[0]), "+f"(d[1]), "+f"(d[2]), "+f"(d[3])
        : "r"(a[0]), "r"(a[1]), "r"(a[2]), "r"(a[3]), "r"(b[0]), "r"(b[1]));
}

template <int BN, bool TRANSB, int EPI>
__device__ __forceinline__
void tgemm_dev(const float* __restrict__ A, const float* __restrict__ Bm,
               const float* __restrict__ bias, const float* __restrict__ resid,
               float* __restrict__ C, int N, int K, int bm, int bn) {
    constexpr int BK   = 16;
    constexpr int NJ   = BN / 16;
    constexpr int BROW = BN + 4;
    constexpr int ASZ  = 128 * 20;
    constexpr int BSZ  = TRANSB ? (BN * 20) : (BK * BROW);

    extern __shared__ unsigned smem_u[];
    unsigned* sA = smem_u;
    unsigned* sB = smem_u + 3 * ASZ;

    const int tid  = threadIdx.x;
    const int lane = tid & 31;
    const int wid  = tid >> 5;
    const int wm   = (wid & 3) * 32;
    const int wn   = (wid >> 2) * (BN / 2);
    const int g    = lane >> 2;
    const int t    = lane & 3;

    float acc[2][NJ][4];
#pragma unroll
    for (int i = 0; i < 2; i++)
#pragma unroll
        for (int j = 0; j < NJ; j++)
#pragma unroll
            for (int r = 0; r < 4; r++) acc[i][j][r] = 0.f;

    const int ar = tid >> 2;
    const int ak = (tid & 3) * 4;
    const int nbR = (BN == 128) ? (tid >> 5) : (tid >> 4);
    const int nbC = (BN == 128) ? ((tid & 31) * 4) : ((tid & 15) * 4);
    const int tbN = tid >> 2;
    const int tbK = (tid & 3) * 4;

    const unsigned sAaddr = (unsigned)__cvta_generic_to_shared(sA);
    const unsigned sBaddr = (unsigned)__cvta_generic_to_shared(sB);

    const int ntiles = K / BK;

    auto issue = [&](int st, int kt) {
        const int k0 = kt * BK;
        unsigned a_s = sAaddr + (st * ASZ) * 4;
        unsigned b_s = sBaddr + (st * BSZ) * 4;
        const float* ap = A + (size_t)(bm + ar) * K + k0 + ak;
        cp16(a_s + (ar * 20 + ak) * 4,        ap,                  true);
        cp16(a_s + ((ar + 64) * 20 + ak) * 4, ap + (size_t)64 * K, true);
        if (TRANSB) {
            int gn0 = bn + tbN;
            const float* bp0 = Bm + (size_t)(gn0 < N ? gn0 : 0) * K + k0 + tbK;
            cp16(b_s + (tbN * 20 + tbK) * 4, bp0, gn0 < N);
            if (BN == 128) {
                int gn1 = gn0 + 64;
                const float* bp1 = Bm + (size_t)(gn1 < N ? gn1 : 0) * K + k0 + tbK;
                cp16(b_s + ((tbN + 64) * 20 + tbK) * 4, bp1, gn1 < N);
            }
        } else {
            const float* bp = Bm + (size_t)(k0 + nbR) * N + bn + nbC;
            cp16(b_s + (nbR * BROW + nbC) * 4, bp, true);
            if (BN == 128)
                cp16(b_s + ((nbR + 8) * BROW + nbC) * 4, bp + (size_t)8 * N, true);
        }
    };

    issue(0, 0); cp_commit();
    issue(1, 1); cp_commit();

    for (int kt = 0; kt < ntiles; kt++) {
        cp_wait1();
        __syncthreads();
        const int cur = kt % 3;
        const unsigned* As = sA + cur * ASZ;
        const unsigned* Bs = sB + cur * BSZ;
#pragma unroll
        for (int ks = 0; ks < 2; ks++) {
            const int k8 = ks * 8;
            unsigned af[2][4], bf[NJ][2];
#pragma unroll
            for (int i = 0; i < 2; i++) {
                const int mr = wm + i * 16 + g;
                af[i][0] = As[mr * 20 + k8 + t];
                af[i][1] = As[(mr + 8) * 20 + k8 + t];
                af[i][2] = As[mr * 20 + k8 + t + 4];
                af[i][3] = As[(mr + 8) * 20 + k8 + t + 4];
            }
#pragma unroll
            for (int j = 0; j < NJ; j++) {
                const int nc = wn + j * 8 + g;
                if (TRANSB) {
                    bf[j][0] = Bs[nc * 20 + k8 + t];
                    bf[j][1] = Bs[nc * 20 + k8 + t + 4];
                } else {
                    bf[j][0] = Bs[(k8 + t) * BROW + nc];
                    bf[j][1] = Bs[(k8 + t + 4) * BROW + nc];
                }
            }
#pragma unroll
            for (int i = 0; i < 2; i++)
#pragma unroll
                for (int j = 0; j < NJ; j++)
                    mma_tf32(acc[i][j], af[i], bf[j]);
        }
        if (kt + 2 < ntiles) issue((kt + 2) % 3, kt + 2);
        cp_commit();
    }

#pragma unroll
    for (int i = 0; i < 2; i++) {
        const int r0 = bm + wm + i * 16 + g;
        const int r1 = r0 + 8;
#pragma unroll
        for (int j = 0; j < NJ; j++) {
            const int c = bn + wn + j * 8 + 2 * t;
            float v00 = acc[i][j][0], v01 = acc[i][j][1];
            float v10 = acc[i][j][2], v11 = acc[i][j][3];
            if (EPI & 1) {
                float bb0 = bias[c], bb1 = bias[c + 1];
                v00 += bb0; v01 += bb1; v10 += bb0; v11 += bb1;
            }
            if (EPI & 2) {
                v00 = gelu_exact(v00); v01 = gelu_exact(v01);
                v10 = gelu_exact(v10); v11 = gelu_exact(v11);
            }
            if (EPI & 4) {
                const float* rp0 = resid + (size_t)r0 * N + c;
                const float* rp1 = resid + (size_t)r1 * N + c;
                v00 += rp0[0]; v01 += rp0[1];
                v10 += rp1[0]; v11 += rp1[1];
            }
            if (EPI & 8) {
                v00 = rtf(v00); v01 = rtf(v01);
                v10 = rtf(v10); v11 = rtf(v11);
            }
            if (!TRANSB) {
                float2 p0; p0.x = v00; p0.y = v01;
                float2 p1; p1.x = v10; p1.y = v11;
                *(float2*)(C + (size_t)r0 * N + c) = p0;
                *(float2*)(C + (size_t)r1 * N + c) = p1;
            } else {
                if (c < N)     { C[(size_t)r0 * N + c]     = v00; C[(size_t)r1 * N + c]     = v10; }
                if (c + 1 < N) { C[(size_t)r0 * N + c + 1] = v01; C[(size_t)r1 * N + c + 1] = v11; }
            }
        }
    }
}

template <int BN, bool TRANSB, int EPI>
__global__ __launch_bounds__(256)
void tgemm_k(const float* __restrict__ A, const float* __restrict__ Bm,
             const float* __restrict__ bias, const float* __restrict__ resid,
             float* __restrict__ C, int N, int K) {
    tgemm_dev<BN, TRANSB, EPI>(A, Bm, bias, resid, C, N, K,
                               blockIdx.x * 128, blockIdx.y * BN);
}

#define SM_G64F  (3 * (128 * 20 + 16 * 68) * 4)    // 43776
#define SM_G128F (3 * (128 * 20 + 16 * 132) * 4)   // 56064
#define SM_G128T (3 * (128 * 20 + 128 * 20) * 4)   // 61440

// ---------------- tgemm64: BM=64, BN=64, 128 threads (chip-filling) -------
// 4 warps (2m x 2n), warp tile 32x32 = 2x4 m16n8k8 atoms. 3-stage cp.async.
#define SM_G64S (3 * (64 * 20 + 16 * 68) * 4)      // 28416

template <int EPI>
__global__ __launch_bounds__(128)
void tgemm64_k(const float* __restrict__ A, const float* __restrict__ Bm,
               const float* __restrict__ bias, const float* __restrict__ resid,
               float* __restrict__ C, int N, int K) {
    constexpr int BK   = 16;
    constexpr int BROW = 68;
    constexpr int ASZ  = 64 * 20;
    constexpr int BSZ  = BK * BROW;

    extern __shared__ unsigned smem_u[];
    unsigned* sA = smem_u;
    unsigned* sB = smem_u + 3 * ASZ;

    const int bm  = blockIdx.x * 64;
    const int bn  = blockIdx.y * 64;
    const int tid = threadIdx.x;
    const int lane = tid & 31;
    const int wid  = tid >> 5;
    const int wm   = (wid & 1) * 32;
    const int wn   = (wid >> 1) * 32;
    const int g    = lane >> 2;
    const int t    = lane & 3;

    float acc[2][4][4];
#pragma unroll
    for (int i = 0; i < 2; i++)
#pragma unroll
        for (int j = 0; j < 4; j++)
#pragma unroll
            for (int r = 0; r < 4; r++) acc[i][j][r] = 0.f;

    // A: 64x16 = 256 f4, 2/thread (cols 0-3 & 8-11 style: ak 0/8)
    const int ar = tid >> 1;              // 0..63
    const int ak = (tid & 1) * 8;         // 0 or 8
    // B: 16x64 = 256 f4, 2/thread (rows nbR, nbR+8)
    const int nbR = tid >> 4;             // 0..7
    const int nbC = (tid & 15) * 4;

    const unsigned sAaddr = (unsigned)__cvta_generic_to_shared(sA);
    const unsigned sBaddr = (unsigned)__cvta_generic_to_shared(sB);

    const int ntiles = K / BK;

    auto issue = [&](int st, int kt) {
        const int k0 = kt * BK;
        unsigned a_s = sAaddr + (st * ASZ) * 4;
        unsigned b_s = sBaddr + (st * BSZ) * 4;
        const float* ap = A + (size_t)(bm + ar) * K + k0 + ak;
        cp16(a_s + (ar * 20 + ak) * 4,     ap,     true);
        cp16(a_s + (ar * 20 + ak + 4) * 4, ap + 4, true);
        const float* bp = Bm + (size_t)(k0 + nbR) * N + bn + nbC;
        cp16(b_s + (nbR * BROW + nbC) * 4,       bp,               true);
        cp16(b_s + ((nbR + 8) * BROW + nbC) * 4, bp + (size_t)8 * N, true);
    };

    issue(0, 0); cp_commit();
    issue(1, 1); cp_commit();

    for (int kt = 0; kt < ntiles; kt++) {
        cp_wait1();
        __syncthreads();
        const int cur = kt % 3;
        const unsigned* As = sA + cur * ASZ;
        const unsigned* Bs = sB + cur * BSZ;
#pragma unroll
        for (int ks = 0; ks < 2; ks++) {
            const int k8 = ks * 8;
            unsigned af[2][4], bf[4][2];
#pragma unroll
            for (int i = 0; i < 2; i++) {
                const int mr = wm + i * 16 + g;
                af[i][0] = As[mr * 20 + k8 + t];
                af[i][1] = As[(mr + 8) * 20 + k8 + t];
                af[i][2] = As[mr * 20 + k8 + t + 4];
                af[i][3] = As[(mr + 8) * 20 + k8 + t + 4];
            }
#pragma unroll
            for (int j = 0; j < 4; j++) {
                const int nc = wn + j * 8 + g;
                bf[j][0] = Bs[(k8 + t) * BROW + nc];
                bf[j][1] = Bs[(k8 + t + 4) * BROW + nc];
            }
#pragma unroll
            for (int i = 0; i < 2; i++)
#pragma unroll
                for (int j = 0; j < 4; j++)
                    mma_tf32(acc[i][j], af[i], bf[j]);
        }
        if (kt + 2 < ntiles) issue((kt + 2) % 3, kt + 2);
        cp_commit();
    }

#pragma unroll
    for (int i = 0; i < 2; i++) {
        const int r0 = bm + wm + i * 16 + g;
        const int r1 = r0 + 8;
#pragma unroll
        for (int j = 0; j < 4; j++) {
            const int c = bn + wn + j * 8 + 2 * t;
            float v00 = acc[i][j][0], v01 = acc[i][j][1];
            float v10 = acc[i][j][2], v11 = acc[i][j][3];
            if (EPI & 1) {
                float bb0 = bias[c], bb1 = bias[c + 1];
                v00 += bb0; v01 += bb1; v10 += bb0; v11 += bb1;
            }
            if (EPI & 2) {
                v00 = gelu_exact(v00); v01 = gelu_exact(v01);
                v10 = gelu_exact(v10); v11 = gelu_exact(v11);
            }
            if (EPI & 4) {
                const float* rp0 = resid + (size_t)r0 * N + c;
                const float* rp1 = resid + (size_t)r1 * N + c;
                v00 += rp0[0]; v01 += rp0[1];
                v10 += rp1[0]; v11 += rp1[1];
            }
            if (EPI & 8) {
                v00 = rtf(v00); v01 = rtf(v01);
                v10 = rtf(v10); v11 = rtf(v11);
            }
            float2 p0; p0.x = v00; p0.y = v01;
            float2 p1; p1.x = v10; p1.y = v11;
            *(float2*)(C + (size_t)r0 * N + c) = p0;
            *(float2*)(C + (size_t)r1 * N + c) = p1;
        }
    }
}

// ---------------- Causal attention: 64q flash tile ----------------
#define ATTN_SMEM (4 * 64 * 68 * 4 + 2 * 64 * 4)

__global__ __launch_bounds__(256)
void attn_kernel(const float* __restrict__ qkv, float* __restrict__ o) {
    extern __shared__ float sm[];
    float (*Qs)[68] = (float(*)[68])sm;
    float (*Ks)[68] = (float(*)[68])(sm + 64 * 68);
    float (*Vs)[68] = (float(*)[68])(sm + 2 * 64 * 68);
    float (*Ss)[68] = (float(*)[68])(sm + 3 * 64 * 68);
    float* ms = sm + 4 * 64 * 68;
    float* ls = ms + 64;

    const int bh  = blockIdx.y;
    const int b   = bh / H_SZ, h = bh % H_SZ;
    const int q0  = blockIdx.x * 64;
    const int tid = threadIdx.x;
    const int tx  = tid & 15, ty = tid >> 4;

    const float* qb = qkv + h * D_SZ;
    const float* kb = qkv + E_SZ + h * D_SZ;
    const float* vb = qkv + 2 * E_SZ + h * D_SZ;

#pragma unroll
    for (int i = 0; i < 4; i++) {
        int f  = tid + i * 256;
        int qq = f & 63, d4 = (f >> 6) * 4;
        float4 t = *(const float4*)(qb + (size_t)(b * T_SZ + q0 + qq) * QKV_LD + d4);
        Qs[d4+0][qq] = t.x * 0.125f; Qs[d4+1][qq] = t.y * 0.125f;
        Qs[d4+2][qq] = t.z * 0.125f; Qs[d4+3][qq] = t.w * 0.125f;
    }
    if (tid < 64) { ms[tid] = -1e30f; ls[tid] = 0.f; }

    float acc[4][4];
#pragma unroll
    for (int r = 0; r < 4; r++)
#pragma unroll
        for (int c = 0; c < 4; c++) acc[r][c] = 0.f;

    for (int kt = 0; kt <= q0; kt += 64) {
#pragma unroll
        for (int i = 0; i < 4; i++) {
            int f  = tid + i * 256;
            int kk = f & 63, d4 = (f >> 6) * 4;
            float4 t = *(const float4*)(kb + (size_t)(b * T_SZ + kt + kk) * QKV_LD + d4);
            Ks[d4+0][kk] = t.x; Ks[d4+1][kk] = t.y;
            Ks[d4+2][kk] = t.z; Ks[d4+3][kk] = t.w;
        }
#pragma unroll
        for (int i = 0; i < 4; i++) {
            int f  = tid + i * 256;
            int kk = f >> 4, d4 = (f & 15) * 4;
            *(float4*)&Vs[kk][d4] =
                *(const float4*)(vb + (size_t)(b * T_SZ + kt + kk) * QKV_LD + d4);
        }
        __syncthreads();

        float s[4][4];
#pragma unroll
        for (int r = 0; r < 4; r++)
#pragma unroll
            for (int c = 0; c < 4; c++) s[r][c] = 0.f;
#pragma unroll 4
        for (int d = 0; d < 64; d++) {
            float4 aq = *(const float4*)&Qs[d][4 * ty];
            float4 bk = *(const float4*)&Ks[d][4 * tx];
            float a[4] = {aq.x, aq.y, aq.z, aq.w};
            float bb[4] = {bk.x, bk.y, bk.z, bk.w};
#pragma unroll
            for (int r = 0; r < 4; r++)
#pragma unroll
                for (int c = 0; c < 4; c++) s[r][c] += a[r] * bb[c];
        }

        const bool diag = (kt == q0);
        float cfl[4];
#pragma unroll
        for (int r = 0; r < 4; r++) {
            const int row = 4 * ty + r;
            if (diag) {
#pragma unroll
                for (int c = 0; c < 4; c++)
                    if (4 * tx + c > row) s[r][c] = -1e30f;
            }
            float mx = fmaxf(fmaxf(s[r][0], s[r][1]), fmaxf(s[r][2], s[r][3]));
#pragma unroll
            for (int off = 1; off < 16; off <<= 1)
                mx = fmaxf(mx, __shfl_xor_sync(0xffffffffu, mx, off));
            const float mold = ms[row];
            const float mnew = fmaxf(mold, mx);
            float ps = 0.f;
#pragma unroll
            for (int c = 0; c < 4; c++) {
                float p = __expf(s[r][c] - mnew);
                Ss[row][4 * tx + c] = p;
                ps += p;
            }
#pragma unroll
            for (int off = 1; off < 16; off <<= 1)
                ps += __shfl_xor_sync(0xffffffffu, ps, off);
            cfl[r] = __expf(mold - mnew);
            if (tx == 0) { ms[row] = mnew; ls[row] = ls[row] * cfl[r] + ps; }
        }
        __syncwarp();

#pragma unroll
        for (int r = 0; r < 4; r++)
#pragma unroll
            for (int c = 0; c < 4; c++) acc[r][c] *= cfl[r];
#pragma unroll 4
        for (int kk = 0; kk < 64; kk++) {
            float4 vv = *(const float4*)&Vs[kk][4 * tx];
#pragma unroll
            for (int r = 0; r < 4; r++) {
                float p = Ss[4 * ty + r][kk];
                acc[r][0] += p * vv.x; acc[r][1] += p * vv.y;
                acc[r][2] += p * vv.z; acc[r][3] += p * vv.w;
            }
        }
        __syncthreads();
    }

#pragma unroll
    for (int r = 0; r < 4; r++) {
        const float inv = 1.f / ls[4 * ty + r];
        float4 t;
        t.x = rtf(acc[r][0] * inv); t.y = rtf(acc[r][1] * inv);
        t.z = rtf(acc[r][2] * inv); t.w = rtf(acc[r][3] * inv);
        *(float4*)(o + (size_t)(b * T_SZ + q0 + 4 * ty + r) * E_SZ + h * D_SZ + 4 * tx) = t;
    }
}

// ---------------- Host orchestration ----------------
extern "C" void kernel_launch(void* const* d_in, const int* in_sizes, int n_in,
                              void* d_out, int out_size) {
    (void)in_sizes; (void)n_in; (void)out_size;
    const int*   tokens = (const int*)  d_in[0];
    const float* wte    = (const float*)d_in[1];
    const float* wpe    = (const float*)d_in[2];
    const float* Wq     = (const float*)d_in[3];
    const float* Wk     = (const float*)d_in[4];
    const float* Wv     = (const float*)d_in[5];
    const float* Wo     = (const float*)d_in[6];
    const float* bo     = (const float*)d_in[7];
    const float* ln1_s  = (const float*)d_in[8];
    const float* ln1_b  = (const float*)d_in[9];
    const float* W1     = (const float*)d_in[10];
    const float* b1     = (const float*)d_in[11];
    const float* W2     = (const float*)d_in[12];
    const float* b2     = (const float*)d_in[13];
    const float* ln2_s  = (const float*)d_in[14];
    const float* ln2_b  = (const float*)d_in[15];
    const float* lnf_s  = (const float*)d_in[16];
    const float* lnf_b  = (const float*)d_in[17];
    float* out = (float*)d_out;

    float *x, *h, *qkv, *att, *m1;
    float *wqkv, *wo, *w1, *w2, *wt;
    cudaGetSymbolAddress((void**)&x,    g_x);
    cudaGetSymbolAddress((void**)&h,    g_h);
    cudaGetSymbolAddress((void**)&qkv,  g_qkv);
    cudaGetSymbolAddress((void**)&att,  g_att);
    cudaGetSymbolAddress((void**)&m1,   g_m1);
    cudaGetSymbolAddress((void**)&wqkv, g_wqkv);
    cudaGetSymbolAddress((void**)&wo,   g_wo);
    cudaGetSymbolAddress((void**)&w1,   g_w1);
    cudaGetSymbolAddress((void**)&w2,   g_w2);
    cudaGetSymbolAddress((void**)&wt,   g_wte);

    cudaFuncSetAttribute(attn_kernel,
                         cudaFuncAttributeMaxDynamicSharedMemorySize, ATTN_SMEM);
    cudaFuncSetAttribute(tgemm_k<128, false, 0>,
                         cudaFuncAttributeMaxDynamicSharedMemorySize, SM_G128F);
    cudaFuncSetAttribute(tgemm_k<128, false, 11>,
                         cudaFuncAttributeMaxDynamicSharedMemorySize, SM_G128F);
    cudaFuncSetAttribute(tgemm_k<128, true, 0>,
                         cudaFuncAttributeMaxDynamicSharedMemorySize, SM_G128T);
    cudaFuncSetAttribute(tgemm64_k<5>,
                         cudaFuncAttributeMaxDynamicSharedMemorySize, SM_G64S);

    // ---- per-launch weight rounding / packing ----
    {
        const int nE = L_SZ * E_SZ * E_SZ / 4;
        const int nF = L_SZ * E_SZ * FF / 4;
        const int nV = V_SZ * E_SZ / 4;
        pack_qkv_kernel<<<(nE + 255) / 256, 256>>>(
            (const float4*)Wq, (const float4*)Wk, (const float4*)Wv, (float4*)wqkv, nE);
        cvt_kernel<<<(nE + 255) / 256, 256>>>((const float4*)Wo, (float4*)wo, nE);
        cvt_kernel<<<(nF + 255) / 256, 256>>>((const float4*)W1, (float4*)w1, nF);
        cvt_kernel<<<(nF + 255) / 256, 256>>>((const float4*)W2, (float4*)w2, nF);
        cvt_kernel<<<(nV + 255) / 256, 256>>>((const float4*)wte, (float4*)wt, nV);
    }

    embed_kernel<<<BT, 192>>>(tokens, wte, wpe, x);

    const dim3 gE64(BT / 64, E_SZ / 64);           // 32 x 12 = 384
    const dim3 gQKV(BT / 128, QKV_LD / 128);       // 16 x 18
    const dim3 gF(BT / 128, FF / 128);             // 16 x 24
    const dim3 gATT(T_SZ / 64, B_SZ * H_SZ);       // 16 x 24
    const dim3 gLOG(BT / 128, (V_SZ + 127) / 128); // 16 x 393

    for (int l = 0; l < L_SZ; l++) {
        const size_t wqOff = (size_t)l * E_SZ * QKV_LD;
        const size_t wOff  = (size_t)l * E_SZ * E_SZ;
        const size_t w1Off = (size_t)l * E_SZ * FF;
        const size_t vOff  = (size_t)l * E_SZ;
        const size_t fOff  = (size_t)l * FF;

        layernorm_kernel<<<BT, 256>>>(x, ln1_s + vOff, ln1_b + vOff, h);
        tgemm_k<128, false, 0><<<gQKV, 256, SM_G128F>>>(h, wqkv + wqOff, nullptr, nullptr,
                                                        qkv, QKV_LD, E_SZ);
        attn_kernel<<<gATT, 256, ATTN_SMEM>>>(qkv, att);
        tgemm64_k<5><<<gE64, 128, SM_G64S>>>(att, wo + wOff, bo + vOff, x, x, E_SZ, E_SZ);
        layernorm_kernel<<<BT, 256>>>(x, ln2_s + vOff, ln2_b + vOff, h);
        tgemm_k<128, false, 11><<<gF, 256, SM_G128F>>>(h, w1 + w1Off, b1 + fOff, nullptr, m1, FF, E_SZ);
        tgemm64_k<5><<<gE64, 128, SM_G64S>>>(m1, w2 + w1Off, b2 + vOff, x, x, E_SZ, FF);
    }

    layernorm_kernel<<<BT, 256>>>(x, lnf_s, lnf_b, h);
    tgemm_k<128, true, 0><<<gLOG, 256, SM_G128T>>>(h, wt, nullptr, nullptr, out, V_SZ, E_SZ);
}

// round 14
// speedup vs baseline: 1.2028x; 1.1364x over previous
#include <cuda_runtime.h>
#include <cuda_fp16.h>
#include <cuda_bf16.h>
#include <math.h>
#include <stdint.h>

// ---------------- Problem constants ----------------
#define V_SZ 50257
#define E_SZ 768
#define H_SZ 12
#define L_SZ 6
#define T_SZ 1024
#define B_SZ 2
#define D_SZ 64
#define BT   (B_SZ * T_SZ)      // 2048
#define FF   (4 * E_SZ)         // 3072
#define QKV_LD (3 * E_SZ)       // 2304

// ---------------- Scratch ----------------
__device__ float  g_x   [BT * E_SZ];
__device__ float  g_h   [BT * E_SZ];
__device__ __half g_hh  [BT * E_SZ];
__device__ float  g_qkv [BT * QKV_LD];
__device__ float  g_att [BT * E_SZ];
__device__ float  g_m1  [BT * FF];
__device__ float  g_wqkv[L_SZ * E_SZ * QKV_LD];
__device__ float  g_wo  [L_SZ * E_SZ * E_SZ];
__device__ float  g_w1  [L_SZ * E_SZ * FF];
__device__ float  g_w2  [L_SZ * E_SZ * FF];
__device__ __half g_wteh[V_SZ * E_SZ];

// ---------------- tf32 helpers ----------------
__device__ __forceinline__ unsigned f2tf(float f) {
    unsigned u;
    asm("cvt.rna.tf32.f32 %0, %1;" : "=r"(u) : "f"(f));
    return u;
}
__device__ __forceinline__ float rtf(float f) { return __uint_as_float(f2tf(f)); }
__device__ __forceinline__ float4 rtf4(float4 v) {
    v.x = rtf(v.x); v.y = rtf(v.y); v.z = rtf(v.z); v.w = rtf(v.w);
    return v;
}

__global__ void cvt_kernel(const float4* __restrict__ src, float4* __restrict__ dst, int n4) {
    int i = blockIdx.x * 256 + threadIdx.x;
    if (i < n4) dst[i] = rtf4(src[i]);
}

// fp32 -> fp16 (rn), 4 elems/thread
__global__ void cvt_half_kernel(const float4* __restrict__ src, uint2* __restrict__ dst, int n4) {
    int i = blockIdx.x * 256 + threadIdx.x;
    if (i >= n4) return;
    float4 v = src[i];
    __half2 h0 = __floats2half2_rn(v.x, v.y);
    __half2 h1 = __floats2half2_rn(v.z, v.w);
    uint2 u;
    u.x = *(unsigned*)&h0;
    u.y = *(unsigned*)&h1;
    dst[i] = u;
}

__global__ void pack_qkv_kernel(const float4* __restrict__ q, const float4* __restrict__ k,
                                const float4* __restrict__ v, float4* __restrict__ dst, int n4) {
    int i = blockIdx.x * 256 + threadIdx.x;
    if (i >= n4) return;
    const int per = E_SZ * E_SZ / 4;
    const int rw  = E_SZ / 4;
    int l = i / per, r = i % per;
    int row = r / rw, c4 = r % rw;
    size_t base = (size_t)l * (E_SZ * QKV_LD / 4) + (size_t)row * (QKV_LD / 4) + c4;
    dst[base]          = rtf4(q[i]);
    dst[base + rw]     = rtf4(k[i]);
    dst[base + 2 * rw] = rtf4(v[i]);
}

// ---------------- Embedding ----------------
__global__ void embed_kernel(const int* __restrict__ tok,
                             const float* __restrict__ wte,
                             const float* __restrict__ wpe,
                             float* __restrict__ x) {
    int row = blockIdx.x;
    int t   = row % T_SZ;
    int tk  = tok[row];
    int e   = threadIdx.x * 4;
    const float4 a = *(const float4*)(wte + (size_t)tk * E_SZ + e);
    const float4 b = *(const float4*)(wpe + (size_t)t  * E_SZ + e);
    float4 o;
    o.x = a.x + b.x; o.y = a.y + b.y; o.z = a.z + b.z; o.w = a.w + b.w;
    *(float4*)(x + (size_t)row * E_SZ + e) = o;
}

// ---------------- LayerNorm (tf32-rounded output) ----------------
__global__ void layernorm_kernel(const float* __restrict__ x,
                                 const float* __restrict__ sc,
                                 const float* __restrict__ bi,
                                 float* __restrict__ out) {
    int row = blockIdx.x;
    const float* xr = x + (size_t)row * E_SZ;
    float lv[3];
    float s = 0.f, sq = 0.f;
#pragma unroll
    for (int i = 0; i < 3; i++) {
        float t = xr[threadIdx.x + i * 256];
        lv[i] = t; s += t; sq += t * t;
    }
#pragma unroll
    for (int o = 16; o > 0; o >>= 1) {
        s  += __shfl_down_sync(0xffffffffu, s,  o);
        sq += __shfl_down_sync(0xffffffffu, sq, o);
    }
    __shared__ float sa[8], sb[8];
    int w = threadIdx.x >> 5, lane = threadIdx.x & 31;
    if (lane == 0) { sa[w] = s; sb[w] = sq; }
    __syncthreads();
    __shared__ float s_mu, s_rstd;
    if (threadIdx.x == 0) {
        float ts = 0.f, tq = 0.f;
#pragma unroll
        for (int i = 0; i < 8; i++) { ts += sa[i]; tq += sb[i]; }
        float mu  = ts * (1.0f / E_SZ);
        float var = tq * (1.0f / E_SZ) - mu * mu;
        s_mu = mu;
        s_rstd = rsqrtf(var + 1e-5f);
    }
    __syncthreads();
    float mu = s_mu, rstd = s_rstd;
#pragma unroll
    for (int i = 0; i < 3; i++) {
        int c = threadIdx.x + i * 256;
        out[(size_t)row * E_SZ + c] = rtf((lv[i] - mu) * rstd * sc[c] + bi[c]);
    }
}

// ---------------- cp.async helpers ----------------
__device__ __forceinline__ void cp16(unsigned sdst, const void* src, bool pred) {
    int sz = pred ? 16 : 0;
    asm volatile("cp.async.cg.shared.global [%0], [%1], 16, %2;\n"
                 :: "r"(sdst), "l"(src), "r"(sz));
}
__device__ __forceinline__ void cp_commit() {
    asm volatile("cp.async.commit_group;\n");
}
__device__ __forceinline__ void cp_wait1() {
    asm volatile("cp.async.wait_group 1;\n");
}

// ---------------- TF32 mma.sync GEMM (128-row tiles) ----------------
__device__ __forceinline__ float gelu_exact(float v) {
    return 0.5f * v * (1.0f + erff(v * 0.70710678118654752f));
}
__device__ __forceinline__ void mma_tf32(float* d, const unsigned* a, const unsigned* b) {
    asm volatile(
        "mma.sync.aligned.m16n8k8.row.col.f32.tf32.tf32.f32 "
        "{%0,%1,%2,%3}, {%4,%5,%6,%7}, {%8,%9}, {%0,%1,%2,%3};"
        : "+f"(d[0]), "+f"(d[1]), "+f"(d[2]), "+f"(d[3])
        : "r"(a[0]), "r"(a[1]), "r"(a[2]), "r"(a[3]), "r"(b[0]), "r"(b[1]));
}
__device__ __forceinline__ void mma_f16(float* d, const unsigned* a, const unsigned* b) {
    asm volatile(
        "mma.sync.aligned.m16n8k16.row.col.f32.f16.f16.f32 "
        "{%0,%1,%2,%3}, {%4,%5,%6,%7}, {%8,%9}, {%0,%1,%2,%3};"
        : "+f"(d[0]), "+f"(d[1]), "+f"(d[2]), "+f"(d[3])
        : "r"(a[0]), "r"(a[1]), "r"(a[2]), "r"(a[3]), "r"(b[0]), "r"(b[1]));
}

template <int BN, int EPI>
__device__ __forceinline__
void tgemm_dev(const float* __restrict__ A, const float* __restrict__ Bm,
               const float* __restrict__ bias, const float* __restrict__ resid,
               float* __restrict__ C, int N, int K, int bm, int bn) {
    constexpr int BK   = 16;
    constexpr int NJ   = BN / 16;
    constexpr int BROW = BN + 4;
    constexpr int ASZ  = 128 * 20;
    constexpr int BSZ  = BK * BROW;

    extern __shared__ unsigned smem_u[];
    unsigned* sA = smem_u;
    unsigned* sB = smem_u + 3 * ASZ;

    const int tid  = threadIdx.x;
    const int lane = tid & 31;
    const int wid  = tid >> 5;
    const int wm   = (wid & 3) * 32;
    const int wn   = (wid >> 2) * (BN / 2);
    const int g    = lane >> 2;
    const int t    = lane & 3;

    float acc[2][NJ][4];
#pragma unroll
    for (int i = 0; i < 2; i++)
#pragma unroll
        for (int j = 0; j < NJ; j++)
#pragma unroll
            for (int r = 0; r < 4; r++) acc[i][j][r] = 0.f;

    const int ar = tid >> 2;
    const int ak = (tid & 3) * 4;
    const int nbR = (BN == 128) ? (tid >> 5) : (tid >> 4);
    const int nbC = (BN == 128) ? ((tid & 31) * 4) : ((tid & 15) * 4);

    const unsigned sAaddr = (unsigned)__cvta_generic_to_shared(sA);
    const unsigned sBaddr = (unsigned)__cvta_generic_to_shared(sB);

    const int ntiles = K / BK;

    auto issue = [&](int st, int kt) {
        const int k0 = kt * BK;
        unsigned a_s = sAaddr + (st * ASZ) * 4;
        unsigned b_s = sBaddr + (st * BSZ) * 4;
        const float* ap = A + (size_t)(bm + ar) * K + k0 + ak;
        cp16(a_s + (ar * 20 + ak) * 4,        ap,                  true);
        cp16(a_s + ((ar + 64) * 20 + ak) * 4, ap + (size_t)64 * K, true);
        const float* bp = Bm + (size_t)(k0 + nbR) * N + bn + nbC;
        cp16(b_s + (nbR * BROW + nbC) * 4, bp, true);
        if (BN == 128)
            cp16(b_s + ((nbR + 8) * BROW + nbC) * 4, bp + (size_t)8 * N, true);
    };

    issue(0, 0); cp_commit();
    issue(1, 1); cp_commit();

    for (int kt = 0; kt < ntiles; kt++) {
        cp_wait1();
        __syncthreads();
        const int cur = kt % 3;
        const unsigned* As = sA + cur * ASZ;
        const unsigned* Bs = sB + cur * BSZ;
#pragma unroll
        for (int ks = 0; ks < 2; ks++) {
            const int k8 = ks * 8;
            unsigned af[2][4], bf[NJ][2];
#pragma unroll
            for (int i = 0; i < 2; i++) {
                const int mr = wm + i * 16 + g;
                af[i][0] = As[mr * 20 + k8 + t];
                af[i][1] = As[(mr + 8) * 20 + k8 + t];
                af[i][2] = As[mr * 20 + k8 + t + 4];
                af[i][3] = As[(mr + 8) * 20 + k8 + t + 4];
            }
#pragma unroll
            for (int j = 0; j < NJ; j++) {
                const int nc = wn + j * 8 + g;
                bf[j][0] = Bs[(k8 + t) * BROW + nc];
                bf[j][1] = Bs[(k8 + t + 4) * BROW + nc];
            }
#pragma unroll
            for (int i = 0; i < 2; i++)
#pragma unroll
                for (int j = 0; j < NJ; j++)
                    mma_tf32(acc[i][j], af[i], bf[j]);
        }
        if (kt + 2 < ntiles) issue((kt + 2) % 3, kt + 2);
        cp_commit();
    }

#pragma unroll
    for (int i = 0; i < 2; i++) {
        const int r0 = bm + wm + i * 16 + g;
        const int r1 = r0 + 8;
#pragma unroll
        for (int j = 0; j < NJ; j++) {
            const int c = bn + wn + j * 8 + 2 * t;
            float v00 = acc[i][j][0], v01 = acc[i][j][1];
            float v10 = acc[i][j][2], v11 = acc[i][j][3];
            if (EPI & 1) {
                float bb0 = bias[c], bb1 = bias[c + 1];
                v00 += bb0; v01 += bb1; v10 += bb0; v11 += bb1;
            }
            if (EPI & 2) {
                v00 = gelu_exact(v00); v01 = gelu_exact(v01);
                v10 = gelu_exact(v10); v11 = gelu_exact(v11);
            }
            if (EPI & 4) {
                const float* rp0 = resid + (size_t)r0 * N + c;
                const float* rp1 = resid + (size_t)r1 * N + c;
                v00 += rp0[0]; v01 += rp0[1];
                v10 += rp1[0]; v11 += rp1[1];
            }
            if (EPI & 8) {
                v00 = rtf(v00); v01 = rtf(v01);
                v10 = rtf(v10); v11 = rtf(v11);
            }
            float2 p0; p0.x = v00; p0.y = v01;
            float2 p1; p1.x = v10; p1.y = v11;
            *(float2*)(C + (size_t)r0 * N + c) = p0;
            *(float2*)(C + (size_t)r1 * N + c) = p1;
        }
    }
}

template <int BN, int EPI>
__global__ __launch_bounds__(256)
void tgemm_k(const float* __restrict__ A, const float* __restrict__ Bm,
             const float* __restrict__ bias, const float* __restrict__ resid,
             float* __restrict__ C, int N, int K) {
    tgemm_dev<BN, EPI>(A, Bm, bias, resid, C, N, K,
                       blockIdx.x * 128, blockIdx.y * BN);
}

#define SM_G128F (3 * (128 * 20 + 16 * 132) * 4)   // 56064

// ---------------- tgemm64: BM=64, BN=64, 128 threads (chip-filling) -------
#define SM_G64S (3 * (64 * 20 + 16 * 68) * 4)      // 28416

template <int EPI>
__global__ __launch_bounds__(128)
void tgemm64_k(const float* __restrict__ A, const float* __restrict__ Bm,
               const float* __restrict__ bias, const float* __restrict__ resid,
               float* __restrict__ C, int N, int K) {
    constexpr int BK   = 16;
    constexpr int BROW = 68;
    constexpr int ASZ  = 64 * 20;
    constexpr int BSZ  = BK * BROW;

    extern __shared__ unsigned smem_u[];
    unsigned* sA = smem_u;
    unsigned* sB = smem_u + 3 * ASZ;

    const int bm  = blockIdx.x * 64;
    const int bn  = blockIdx.y * 64;
    const int tid = threadIdx.x;
    const int lane = tid & 31;
    const int wid  = tid >> 5;
    const int wm   = (wid & 1) * 32;
    const int wn   = (wid >> 1) * 32;
    const int g    = lane >> 2;
    const int t    = lane & 3;

    float acc[2][4][4];
#pragma unroll
    for (int i = 0; i < 2; i++)
#pragma unroll
        for (int j = 0; j < 4; j++)
#pragma unroll
            for (int r = 0; r < 4; r++) acc[i][j][r] = 0.f;

    const int ar = tid >> 1;
    const int ak = (tid & 1) * 8;
    const int nbR = tid >> 4;
    const int nbC = (tid & 15) * 4;

    const unsigned sAaddr = (unsigned)__cvta_generic_to_shared(sA);
    const unsigned sBaddr = (unsigned)__cvta_generic_to_shared(sB);

    const int ntiles = K / BK;

    auto issue = [&](int st, int kt) {
        const int k0 = kt * BK;
        unsigned a_s = sAaddr + (st * ASZ) * 4;
        unsigned b_s = sBaddr + (st * BSZ) * 4;
        const float* ap = A + (size_t)(bm + ar) * K + k0 + ak;
        cp16(a_s + (ar * 20 + ak) * 4,     ap,     true);
        cp16(a_s + (ar * 20 + ak + 4) * 4, ap + 4, true);
        const float* bp = Bm + (size_t)(k0 + nbR) * N + bn + nbC;
        cp16(b_s + (nbR * BROW + nbC) * 4,       bp,               true);
        cp16(b_s + ((nbR + 8) * BROW + nbC) * 4, bp + (size_t)8 * N, true);
    };

    issue(0, 0); cp_commit();
    issue(1, 1); cp_commit();

    for (int kt = 0; kt < ntiles; kt++) {
        cp_wait1();
        __syncthreads();
        const int cur = kt % 3;
        const unsigned* As = sA + cur * ASZ;
        const unsigned* Bs = sB + cur * BSZ;
#pragma unroll
        for (int ks = 0; ks < 2; ks++) {
            const int k8 = ks * 8;
            unsigned af[2][4], bf[4][2];
#pragma unroll
            for (int i = 0; i < 2; i++) {
                const int mr = wm + i * 16 + g;
                af[i][0] = As[mr * 20 + k8 + t];
                af[i][1] = As[(mr + 8) * 20 + k8 + t];
                af[i][2] = As[mr * 20 + k8 + t + 4];
                af[i][3] = As[(mr + 8) * 20 + k8 + t + 4];
            }
#pragma unroll
            for (int j = 0; j < 4; j++) {
                const int nc = wn + j * 8 + g;
                bf[j][0] = Bs[(k8 + t) * BROW + nc];
                bf[j][1] = Bs[(k8 + t + 4) * BROW + nc];
            }
#pragma unroll
            for (int i = 0; i < 2; i++)
#pragma unroll
                for (int j = 0; j < 4; j++)
                    mma_tf32(acc[i][j], af[i], bf[j]);
        }
        if (kt + 2 < ntiles) issue((kt + 2) % 3, kt + 2);
        cp_commit();
    }

#pragma unroll
    for (int i = 0; i < 2; i++) {
        const int r0 = bm + wm + i * 16 + g;
        const int r1 = r0 + 8;
#pragma unroll
        for (int j = 0; j < 4; j++) {
            const int c = bn + wn + j * 8 + 2 * t;
            float v00 = acc[i][j][0], v01 = acc[i][j][1];
            float v10 = acc[i][j][2], v11 = acc[i][j][3];
            if (EPI & 1) {
                float bb0 = bias[c], bb1 = bias[c + 1];
                v00 += bb0; v01 += bb1; v10 += bb0; v11 += bb1;
            }
            if (EPI & 2) {
                v00 = gelu_exact(v00); v01 = gelu_exact(v01);
                v10 = gelu_exact(v10); v11 = gelu_exact(v11);
            }
            if (EPI & 4) {
                const float* rp0 = resid + (size_t)r0 * N + c;
                const float* rp1 = resid + (size_t)r1 * N + c;
                v00 += rp0[0]; v01 += rp0[1];
                v10 += rp1[0]; v11 += rp1[1];
            }
            if (EPI & 8) {
                v00 = rtf(v00); v01 = rtf(v01);
                v10 = rtf(v10); v11 = rtf(v11);
            }
            float2 p0; p0.x = v00; p0.y = v01;
            float2 p1; p1.x = v10; p1.y = v11;
            *(float2*)(C + (size_t)r0 * N + c) = p0;
            *(float2*)(C + (size_t)r1 * N + c) = p1;
        }
    }
}

// ---------------- fp16 logits GEMM: BM=128, BN=128, BK=32 ----------------
// D[2048, V] = h_fp16 @ wte_fp16^T; fp32 accumulate.
// 8 warps (4m x 2n), warp tile 32x64 = 2 m-atoms x 8 n-atoms, m16n8k16.
#define HROW 40                                     // halfs per smem row
#define SM_LOGH (3 * 2 * 128 * HROW * 2)            // 61440 bytes

__global__ __launch_bounds__(256)
void logits_h_k(const __half* __restrict__ A, const __half* __restrict__ Bm,
                float* __restrict__ C, int N, int K) {
    constexpr int BK  = 32;
    constexpr int ASZ = 128 * HROW;                 // halfs per stage

    extern __shared__ __half smem_h[];
    __half* sA = smem_h;
    __half* sB = smem_h + 3 * ASZ;

    const int bm  = blockIdx.x * 128;
    const int bn  = blockIdx.y * 128;
    const int tid = threadIdx.x;
    const int lane = tid & 31;
    const int wid  = tid >> 5;
    const int wm   = (wid & 3) * 32;
    const int wn   = (wid >> 2) * 64;
    const int g    = lane >> 2;
    const int t    = lane & 3;

    float acc[2][8][4];
#pragma unroll
    for (int i = 0; i < 2; i++)
#pragma unroll
        for (int j = 0; j < 8; j++)
#pragma unroll
            for (int r = 0; r < 4; r++) acc[i][j][r] = 0.f;

    const unsigned sAaddr = (unsigned)__cvta_generic_to_shared(sA);
    const unsigned sBaddr = (unsigned)__cvta_generic_to_shared(sB);

    const int ntiles = K / BK;                      // 24

    // per stage: A 128x32h + B 128x32h = 1024 x 16B chunks, 4/thread
    auto issue = [&](int st, int kt) {
#pragma unroll
        for (int i = 0; i < 4; i++) {
            int f   = tid + i * 256;                // 0..1023
            int isB = f >> 9;
            int row = (f >> 2) & 127;
            int c   = (f & 3) * 8;                  // half col
            const __half* src;
            bool pred = true;
            if (isB) {
                int gn = bn + row;
                if (gn >= N) { gn = 0; pred = false; }   // zero-fill OOB rows
                src = Bm + (size_t)gn * K + kt * BK + c;
            } else {
                src = A + (size_t)(bm + row) * K + kt * BK + c;
            }
            unsigned dst = (isB ? sBaddr : sAaddr) + (st * ASZ + row * HROW + c) * 2;
            cp16(dst, src, pred);
        }
    };

    issue(0, 0); cp_commit();
    issue(1, 1); cp_commit();

    for (int kt = 0; kt < ntiles; kt++) {
        cp_wait1();
        __syncthreads();
        const int cur = kt % 3;
        const __half* As = sA + cur * ASZ;
        const __half* Bs = sB + cur * ASZ;
#pragma unroll
        for (int ks = 0; ks < 2; ks++) {
            const int kk0 = ks * 16;
            unsigned af[2][4], bf[8][2];
#pragma unroll
            for (int i = 0; i < 2; i++) {
                const int mr = wm + i * 16 + g;
                af[i][0] = *(const unsigned*)&As[mr * HROW + kk0 + 2 * t];
                af[i][1] = *(const unsigned*)&As[(mr + 8) * HROW + kk0 + 2 * t];
                af[i][2] = *(const unsigned*)&As[mr * HROW + kk0 + 2 * t + 8];
                af[i][3] = *(const unsigned*)&As[(mr + 8) * HROW + kk0 + 2 * t + 8];
            }
#pragma unroll
            for (int j = 0; j < 8; j++) {
                const int nc = wn + j * 8 + g;
                bf[j][0] = *(const unsigned*)&Bs[nc * HROW + kk0 + 2 * t];
                bf[j][1] = *(const unsigned*)&Bs[nc * HROW + kk0 + 2 * t + 8];
            }
#pragma unroll
            for (int i = 0; i < 2; i++)
#pragma unroll
                for (int j = 0; j < 8; j++)
                    mma_f16(acc[i][j], af[i], bf[j]);
        }
        if (kt + 2 < ntiles) issue((kt + 2) % 3, kt + 2);
        cp_commit();
    }

    // epilogue: scalar bounds-checked stores (V odd)
#pragma unroll
    for (int i = 0; i < 2; i++) {
        const int r0 = bm + wm + i * 16 + g;
        const int r1 = r0 + 8;
        float* cp0 = C + (size_t)r0 * N;
        float* cp1 = C + (size_t)r1 * N;
#pragma unroll
        for (int j = 0; j < 8; j++) {
            const int c = bn + wn + j * 8 + 2 * t;
            if (c < N)     { cp0[c]     = acc[i][j][0]; cp1[c]     = acc[i][j][2]; }
            if (c + 1 < N) { cp0[c + 1] = acc[i][j][1]; cp1[c + 1] = acc[i][j][3]; }
        }
    }
}

// ---------------- Causal attention: 64q flash tile ----------------
#define ATTN_SMEM (4 * 64 * 68 * 4 + 2 * 64 * 4)

__global__ __launch_bounds__(256)
void attn_kernel(const float* __restrict__ qkv, float* __restrict__ o) {
    extern __shared__ float sm[];
    float (*Qs)[68] = (float(*)[68])sm;
    float (*Ks)[68] = (float(*)[68])(sm + 64 * 68);
    float (*Vs)[68] = (float(*)[68])(sm + 2 * 64 * 68);
    float (*Ss)[68] = (float(*)[68])(sm + 3 * 64 * 68);
    float* ms = sm + 4 * 64 * 68;
    float* ls = ms + 64;

    const int bh  = blockIdx.y;
    const int b   = bh / H_SZ, h = bh % H_SZ;
    const int q0  = blockIdx.x * 64;
    const int tid = threadIdx.x;
    const int tx  = tid & 15, ty = tid >> 4;

    const float* qb = qkv + h * D_SZ;
    const float* kb = qkv + E_SZ + h * D_SZ;
    const float* vb = qkv + 2 * E_SZ + h * D_SZ;

#pragma unroll
    for (int i = 0; i < 4; i++) {
        int f  = tid + i * 256;
        int qq = f & 63, d4 = (f >> 6) * 4;
        float4 t = *(const float4*)(qb + (size_t)(b * T_SZ + q0 + qq) * QKV_LD + d4);
        Qs[d4+0][qq] = t.x * 0.125f; Qs[d4+1][qq] = t.y * 0.125f;
        Qs[d4+2][qq] = t.z * 0.125f; Qs[d4+3][qq] = t.w * 0.125f;
    }
    if (tid < 64) { ms[tid] = -1e30f; ls[tid] = 0.f; }

    float acc[4][4];
#pragma unroll
    for (int r = 0; r < 4; r++)
#pragma unroll
        for (int c = 0; c < 4; c++) acc[r][c] = 0.f;

    for (int kt = 0; kt <= q0; kt += 64) {
#pragma unroll
        for (int i = 0; i < 4; i++) {
            int f  = tid + i * 256;
            int kk = f & 63, d4 = (f >> 6) * 4;
            float4 t = *(const float4*)(kb + (size_t)(b * T_SZ + kt + kk) * QKV_LD + d4);
            Ks[d4+0][kk] = t.x; Ks[d4+1][kk] = t.y;
            Ks[d4+2][kk] = t.z; Ks[d4+3][kk] = t.w;
        }
#pragma unroll
        for (int i = 0; i < 4; i++) {
            int f  = tid + i * 256;
            int kk = f >> 4, d4 = (f & 15) * 4;
            *(float4*)&Vs[kk][d4] =
                *(const float4*)(vb + (size_t)(b * T_SZ + kt + kk) * QKV_LD + d4);
        }
        __syncthreads();

        float s[4][4];
#pragma unroll
        for (int r = 0; r < 4; r++)
#pragma unroll
            for (int c = 0; c < 4; c++) s[r][c] = 0.f;
#pragma unroll 4
        for (int d = 0; d < 64; d++) {
            float4 aq = *(const float4*)&Qs[d][4 * ty];
            float4 bk = *(const float4*)&Ks[d][4 * tx];
            float a[4] = {aq.x, aq.y, aq.z, aq.w};
            float bb[4] = {bk.x, bk.y, bk.z, bk.w};
#pragma unroll
            for (int r = 0; r < 4; r++)
#pragma unroll
                for (int c = 0; c < 4; c++) s[r][c] += a[r] * bb[c];
        }

        const bool diag = (kt == q0);
        float cfl[4];
#pragma unroll
        for (int r = 0; r < 4; r++) {
            const int row = 4 * ty + r;
            if (diag) {
#pragma unroll
                for (int c = 0; c < 4; c++)
                    if (4 * tx + c > row) s[r][c] = -1e30f;
            }
            float mx = fmaxf(fmaxf(s[r][0], s[r][1]), fmaxf(s[r][2], s[r][3]));
#pragma unroll
            for (int off = 1; off < 16; off <<= 1)
                mx = fmaxf(mx, __shfl_xor_sync(0xffffffffu, mx, off));
            const float mold = ms[row];
            const float mnew = fmaxf(mold, mx);
            float ps = 0.f;
#pragma unroll
            for (int c = 0; c < 4; c++) {
                float p = __expf(s[r][c] - mnew);
                Ss[row][4 * tx + c] = p;
                ps += p;
            }
#pragma unroll
            for (int off = 1; off < 16; off <<= 1)
                ps += __shfl_xor_sync(0xffffffffu, ps, off);
            cfl[r] = __expf(mold - mnew);
            if (tx == 0) { ms[row] = mnew; ls[row] = ls[row] * cfl[r] + ps; }
        }
        __syncwarp();

#pragma unroll
        for (int r = 0; r < 4; r++)
#pragma unroll
            for (int c = 0; c < 4; c++) acc[r][c] *= cfl[r];
#pragma unroll 4
        for (int kk = 0; kk < 64; kk++) {
            float4 vv = *(const float4*)&Vs[kk][4 * tx];
#pragma unroll
            for (int r = 0; r < 4; r++) {
                float p = Ss[4 * ty + r][kk];
                acc[r][0] += p * vv.x; acc[r][1] += p * vv.y;
                acc[r][2] += p * vv.z; acc[r][3] += p * vv.w;
            }
        }
        __syncthreads();
    }

#pragma unroll
    for (int r = 0; r < 4; r++) {
        const float inv = 1.f / ls[4 * ty + r];
        float4 t;
        t.x = rtf(acc[r][0] * inv); t.y = rtf(acc[r][1] * inv);
        t.z = rtf(acc[r][2] * inv); t.w = rtf(acc[r][3] * inv);
        *(float4*)(o + (size_t)(b * T_SZ + q0 + 4 * ty + r) * E_SZ + h * D_SZ + 4 * tx) = t;
    }
}

// ---------------- Host orchestration ----------------
extern "C" void kernel_launch(void* const* d_in, const int* in_sizes, int n_in,
                              void* d_out, int out_size) {
    (void)in_sizes; (void)n_in; (void)out_size;
    const int*   tokens = (const int*)  d_in[0];
    const float* wte    = (const float*)d_in[1];
    const float* wpe    = (const float*)d_in[2];
    const float* Wq     = (const float*)d_in[3];
    const float* Wk     = (const float*)d_in[4];
    const float* Wv     = (const float*)d_in[5];
    const float* Wo     = (const float*)d_in[6];
    const float* bo     = (const float*)d_in[7];
    const float* ln1_s  = (const float*)d_in[8];
    const float* ln1_b  = (const float*)d_in[9];
    const float* W1     = (const float*)d_in[10];
    const float* b1     = (const float*)d_in[11];
    const float* W2     = (const float*)d_in[12];
    const float* b2     = (const float*)d_in[13];
    const float* ln2_s  = (const float*)d_in[14];
    const float* ln2_b  = (const float*)d_in[15];
    const float* lnf_s  = (const float*)d_in[16];
    const float* lnf_b  = (const float*)d_in[17];
    float* out = (float*)d_out;

    float *x, *h, *qkv, *att, *m1;
    float *wqkv, *wo, *w1, *w2;
    __half *wteh, *hh;
    cudaGetSymbolAddress((void**)&x,    g_x);
    cudaGetSymbolAddress((void**)&h,    g_h);
    cudaGetSymbolAddress((void**)&hh,   g_hh);
    cudaGetSymbolAddress((void**)&qkv,  g_qkv);
    cudaGetSymbolAddress((void**)&att,  g_att);
    cudaGetSymbolAddress((void**)&m1,   g_m1);
    cudaGetSymbolAddress((void**)&wqkv, g_wqkv);
    cudaGetSymbolAddress((void**)&wo,   g_wo);
    cudaGetSymbolAddress((void**)&w1,   g_w1);
    cudaGetSymbolAddress((void**)&w2,   g_w2);
    cudaGetSymbolAddress((void**)&wteh, g_wteh);

    cudaFuncSetAttribute(attn_kernel,
                         cudaFuncAttributeMaxDynamicSharedMemorySize, ATTN_SMEM);
    cudaFuncSetAttribute(tgemm_k<128, 0>,
                         cudaFuncAttributeMaxDynamicSharedMemorySize, SM_G128F);
    cudaFuncSetAttribute(tgemm_k<128, 11>,
                         cudaFuncAttributeMaxDynamicSharedMemorySize, SM_G128F);
    cudaFuncSetAttribute(tgemm64_k<5>,
                         cudaFuncAttributeMaxDynamicSharedMemorySize, SM_G64S);
    cudaFuncSetAttribute(logits_h_k,
                         cudaFuncAttributeMaxDynamicSharedMemorySize, SM_LOGH);

    // ---- per-launch weight rounding / packing ----
    {
        const int nE = L_SZ * E_SZ * E_SZ / 4;
        const int nF = L_SZ * E_SZ * FF / 4;
        const int nV = V_SZ * E_SZ / 4;
        pack_qkv_kernel<<<(nE + 255) / 256, 256>>>(
            (const float4*)Wq, (const float4*)Wk, (const float4*)Wv, (float4*)wqkv, nE);
        cvt_kernel<<<(nE + 255) / 256, 256>>>((const float4*)Wo, (float4*)wo, nE);
        cvt_kernel<<<(nF + 255) / 256, 256>>>((const float4*)W1, (float4*)w1, nF);
        cvt_kernel<<<(nF + 255) / 256, 256>>>((const float4*)W2, (float4*)w2, nF);
        cvt_half_kernel<<<(nV + 255) / 256, 256>>>((const float4*)wte, (uint2*)wteh, nV);
    }

    embed_kernel<<<BT, 192>>>(tokens, wte, wpe, x);

    const dim3 gE64(BT / 64, E_SZ / 64);           // 32 x 12 = 384
    const dim3 gQKV(BT / 128, QKV_LD / 128);       // 16 x 18
    const dim3 gF(BT / 128, FF / 128);             // 16 x 24
    const dim3 gATT(T_SZ / 64, B_SZ * H_SZ);       // 16 x 24
    const dim3 gLOG(BT / 128, (V_SZ + 127) / 128); // 16 x 393

    for (int l = 0; l < L_SZ; l++) {
        const size_t wqOff = (size_t)l * E_SZ * QKV_LD;
        const size_t wOff  = (size_t)l * E_SZ * E_SZ;
        const size_t w1Off = (size_t)l * E_SZ * FF;
        const size_t vOff  = (size_t)l * E_SZ;
        const size_t fOff  = (size_t)l * FF;

        layernorm_kernel<<<BT, 256>>>(x, ln1_s + vOff, ln1_b + vOff, h);
        tgemm_k<128, 0><<<gQKV, 256, SM_G128F>>>(h, wqkv + wqOff, nullptr, nullptr,
                                                 qkv, QKV_LD, E_SZ);
        attn_kernel<<<gATT, 256, ATTN_SMEM>>>(qkv, att);
        tgemm64_k<5><<<gE64, 128, SM_G64S>>>(att, wo + wOff, bo + vOff, x, x, E_SZ, E_SZ);
        layernorm_kernel<<<BT, 256>>>(x, ln2_s + vOff, ln2_b + vOff, h);
        tgemm_k<128, 11><<<gF, 256, SM_G128F>>>(h, w1 + w1Off, b1 + fOff, nullptr, m1, FF, E_SZ);
        tgemm64_k<5><<<gE64, 128, SM_G64S>>>(m1, w2 + w1Off, b2 + vOff, x, x, E_SZ, FF);
    }

    layernorm_kernel<<<BT, 256>>>(x, lnf_s, lnf_b, h);
    cvt_half_kernel<<<(BT * E_SZ / 4 + 255) / 256, 256>>>((const float4*)h, (uint2*)hh,
                                                          BT * E_SZ / 4);
    logits_h_k<<<gLOG, 256, SM_LOGH>>>(hh, wteh, out, V_SZ, E_SZ);
}

// round 15
// speedup vs baseline: 1.5564x; 1.2940x over previous
#include <cuda_runtime.h>
#include <cuda_fp16.h>
#include <math.h>
#include <stdint.h>

// ---------------- Problem constants ----------------
#define V_SZ 50257
#define E_SZ 768
#define H_SZ 12
#define L_SZ 6
#define T_SZ 1024
#define B_SZ 2
#define D_SZ 64
#define BT   (B_SZ * T_SZ)      // 2048
#define FF   (4 * E_SZ)         // 3072
#define QKV_LD (3 * E_SZ)       // 2304

// ---------------- Scratch ----------------
__device__ float  g_x    [BT * E_SZ];
__device__ __half g_hh   [BT * E_SZ];      // LN outputs (half)
__device__ float  g_qkv  [BT * QKV_LD];
__device__ __half g_atth [BT * E_SZ];
__device__ __half g_m1h  [BT * FF];
// transposed fp16 weights: [N][K]
__device__ __half g_wqkvT[L_SZ * QKV_LD * E_SZ];
__device__ __half g_woT  [L_SZ * E_SZ * E_SZ];
__device__ __half g_w1T  [L_SZ * FF * E_SZ];
__device__ __half g_w2T  [L_SZ * E_SZ * FF];
__device__ __half g_wteh [V_SZ * E_SZ];

// ---------------- converts ----------------
// fp32 -> fp16 (rn), 4 elems/thread (no transpose; for wte)
__global__ void cvt_half_kernel(const float4* __restrict__ src, uint2* __restrict__ dst, int n4) {
    int i = blockIdx.x * 256 + threadIdx.x;
    if (i >= n4) return;
    float4 v = src[i];
    __half2 h0 = __floats2half2_rn(v.x, v.y);
    __half2 h1 = __floats2half2_rn(v.z, v.w);
    uint2 u;
    u.x = *(unsigned*)&h0;
    u.y = *(unsigned*)&h1;
    dst[i] = u;
}

// transpose-convert: src [K][N] fp32 -> dst [N][K] half.  block 32x8, grid (N/32, K/32, L)
__global__ void tr_half_kernel(const float* __restrict__ src, __half* __restrict__ dst,
                               int K, int N, size_t srcLS, size_t dstLS) {
    __shared__ float tile[32][33];
    const float* s = src + blockIdx.z * srcLS;
    __half* d = dst + blockIdx.z * dstLS;
    int n0 = blockIdx.x * 32, k0 = blockIdx.y * 32;
    int tx = threadIdx.x, ty = threadIdx.y;
#pragma unroll
    for (int j = 0; j < 4; j++)
        tile[ty + j * 8][tx] = s[(size_t)(k0 + ty + j * 8) * N + n0 + tx];
    __syncthreads();
#pragma unroll
    for (int j = 0; j < 4; j++)
        d[(size_t)(n0 + ty + j * 8) * K + k0 + tx] = __float2half_rn(tile[tx][ty + j * 8]);
}

// ---------------- Embedding ----------------
__global__ void embed_kernel(const int* __restrict__ tok,
                             const float* __restrict__ wte,
                             const float* __restrict__ wpe,
                             float* __restrict__ x) {
    int row = blockIdx.x;
    int t   = row % T_SZ;
    int tk  = tok[row];
    int e   = threadIdx.x * 4;
    const float4 a = *(const float4*)(wte + (size_t)tk * E_SZ + e);
    const float4 b = *(const float4*)(wpe + (size_t)t  * E_SZ + e);
    float4 o;
    o.x = a.x + b.x; o.y = a.y + b.y; o.z = a.z + b.z; o.w = a.w + b.w;
    *(float4*)(x + (size_t)row * E_SZ + e) = o;
}

// ---------------- LayerNorm: fp32 in -> fp16 out ----------------
__global__ void layernorm_kernel(const float* __restrict__ x,
                                 const float* __restrict__ sc,
                                 const float* __restrict__ bi,
                                 __half* __restrict__ out) {
    int row = blockIdx.x;
    const float* xr = x + (size_t)row * E_SZ;
    float lv[3];
    float s = 0.f, sq = 0.f;
#pragma unroll
    for (int i = 0; i < 3; i++) {
        float t = xr[threadIdx.x + i * 256];
        lv[i] = t; s += t; sq += t * t;
    }
#pragma unroll
    for (int o = 16; o > 0; o >>= 1) {
        s  += __shfl_down_sync(0xffffffffu, s,  o);
        sq += __shfl_down_sync(0xffffffffu, sq, o);
    }
    __shared__ float sa[8], sb[8];
    int w = threadIdx.x >> 5, lane = threadIdx.x & 31;
    if (lane == 0) { sa[w] = s; sb[w] = sq; }
    __syncthreads();
    __shared__ float s_mu, s_rstd;
    if (threadIdx.x == 0) {
        float ts = 0.f, tq = 0.f;
#pragma unroll
        for (int i = 0; i < 8; i++) { ts += sa[i]; tq += sb[i]; }
        float mu  = ts * (1.0f / E_SZ);
        float var = tq * (1.0f / E_SZ) - mu * mu;
        s_mu = mu;
        s_rstd = rsqrtf(var + 1e-5f);
    }
    __syncthreads();
    float mu = s_mu, rstd = s_rstd;
#pragma unroll
    for (int i = 0; i < 3; i++) {
        int c = threadIdx.x + i * 256;
        out[(size_t)row * E_SZ + c] = __float2half_rn((lv[i] - mu) * rstd * sc[c] + bi[c]);
    }
}

// ---------------- cp.async helpers ----------------
__device__ __forceinline__ void cp16(unsigned sdst, const void* src, bool pred) {
    int sz = pred ? 16 : 0;
    asm volatile("cp.async.cg.shared.global [%0], [%1], 16, %2;\n"
                 :: "r"(sdst), "l"(src), "r"(sz));
}
__device__ __forceinline__ void cp_commit() {
    asm volatile("cp.async.commit_group;\n");
}
__device__ __forceinline__ void cp_wait1() {
    asm volatile("cp.async.wait_group 1;\n");
}

__device__ __forceinline__ float gelu_exact(float v) {
    return 0.5f * v * (1.0f + erff(v * 0.70710678118654752f));
}
__device__ __forceinline__ void mma_f16(float* d, const unsigned* a, const unsigned* b) {
    asm volatile(
        "mma.sync.aligned.m16n8k16.row.col.f32.f16.f16.f32 "
        "{%0,%1,%2,%3}, {%4,%5,%6,%7}, {%8,%9}, {%0,%1,%2,%3};"
        : "+f"(d[0]), "+f"(d[1]), "+f"(d[2]), "+f"(d[3])
        : "r"(a[0]), "r"(a[1]), "r"(a[2]), "r"(a[3]), "r"(b[0]), "r"(b[1]));
}

#define HROW 40                                     // halfs per smem row (32 + 8 pad)

// ---------------- hgemm: BM=128, BN=128, BK=32, 256 thr ----------------
// C[M,N] = A[M,K](half) @ B[N,K](half)^T, fp32 acc.
// EPI: 1=+bias, 2=GELU, 4=+resid(fp32).  OUTH: write half to Ch else fp32 to C.
#define SM_H128 (3 * 2 * 128 * HROW * 2)            // 61440

template <int EPI, bool OUTH>
__global__ __launch_bounds__(256)
void hgemm_k(const __half* __restrict__ A, const __half* __restrict__ B,
             const float* __restrict__ bias, const float* __restrict__ resid,
             float* __restrict__ C, __half* __restrict__ Ch, int N, int K) {
    constexpr int BK  = 32;
    constexpr int ASZ = 128 * HROW;

    extern __shared__ __half smem_h[];
    __half* sA = smem_h;
    __half* sB = smem_h + 3 * ASZ;

    const int bm  = blockIdx.x * 128;
    const int bn  = blockIdx.y * 128;
    const int tid = threadIdx.x;
    const int lane = tid & 31;
    const int wid  = tid >> 5;
    const int wm   = (wid & 3) * 32;
    const int wn   = (wid >> 2) * 64;
    const int g    = lane >> 2;
    const int t    = lane & 3;

    float acc[2][8][4];
#pragma unroll
    for (int i = 0; i < 2; i++)
#pragma unroll
        for (int j = 0; j < 8; j++)
#pragma unroll
            for (int r = 0; r < 4; r++) acc[i][j][r] = 0.f;

    const unsigned sAaddr = (unsigned)__cvta_generic_to_shared(sA);
    const unsigned sBaddr = (unsigned)__cvta_generic_to_shared(sB);
    const int ntiles = K / BK;

    auto issue = [&](int st, int kt) {
#pragma unroll
        for (int i = 0; i < 4; i++) {
            int f   = tid + i * 256;
            int isB = f >> 9;
            int row = (f >> 2) & 127;
            int c   = (f & 3) * 8;
            const __half* src = (isB ? B + (size_t)(bn + row) * K
                                     : A + (size_t)(bm + row) * K) + kt * BK + c;
            unsigned dst = (isB ? sBaddr : sAaddr) + (st * ASZ + row * HROW + c) * 2;
            cp16(dst, src, true);
        }
    };

    issue(0, 0); cp_commit();
    issue(1, 1); cp_commit();

    for (int kt = 0; kt < ntiles; kt++) {
        cp_wait1();
        __syncthreads();
        const int cur = kt % 3;
        const __half* As = sA + cur * ASZ;
        const __half* Bs = sB + cur * ASZ;
#pragma unroll
        for (int ks = 0; ks < 2; ks++) {
            const int kk0 = ks * 16;
            unsigned af[2][4], bf[8][2];
#pragma unroll
            for (int i = 0; i < 2; i++) {
                const int mr = wm + i * 16 + g;
                af[i][0] = *(const unsigned*)&As[mr * HROW + kk0 + 2 * t];
                af[i][1] = *(const unsigned*)&As[(mr + 8) * HROW + kk0 + 2 * t];
                af[i][2] = *(const unsigned*)&As[mr * HROW + kk0 + 2 * t + 8];
                af[i][3] = *(const unsigned*)&As[(mr + 8) * HROW + kk0 + 2 * t + 8];
            }
#pragma unroll
            for (int j = 0; j < 8; j++) {
                const int nc = wn + j * 8 + g;
                bf[j][0] = *(const unsigned*)&Bs[nc * HROW + kk0 + 2 * t];
                bf[j][1] = *(const unsigned*)&Bs[nc * HROW + kk0 + 2 * t + 8];
            }
#pragma unroll
            for (int i = 0; i < 2; i++)
#pragma unroll
                for (int j = 0; j < 8; j++)
                    mma_f16(acc[i][j], af[i], bf[j]);
        }
        if (kt + 2 < ntiles) issue((kt + 2) % 3, kt + 2);
        cp_commit();
    }

#pragma unroll
    for (int i = 0; i < 2; i++) {
        const int r0 = bm + wm + i * 16 + g;
        const int r1 = r0 + 8;
#pragma unroll
        for (int j = 0; j < 8; j++) {
            const int c = bn + wn + j * 8 + 2 * t;
            float v00 = acc[i][j][0], v01 = acc[i][j][1];
            float v10 = acc[i][j][2], v11 = acc[i][j][3];
            if (EPI & 1) {
                float bb0 = bias[c], bb1 = bias[c + 1];
                v00 += bb0; v01 += bb1; v10 += bb0; v11 += bb1;
            }
            if (EPI & 2) {
                v00 = gelu_exact(v00); v01 = gelu_exact(v01);
                v10 = gelu_exact(v10); v11 = gelu_exact(v11);
            }
            if (EPI & 4) {
                const float* rp0 = resid + (size_t)r0 * N + c;
                const float* rp1 = resid + (size_t)r1 * N + c;
                v00 += rp0[0]; v01 += rp0[1];
                v10 += rp1[0]; v11 += rp1[1];
            }
            if (OUTH) {
                __half2 p0 = __floats2half2_rn(v00, v01);
                __half2 p1 = __floats2half2_rn(v10, v11);
                *(__half2*)(Ch + (size_t)r0 * N + c) = p0;
                *(__half2*)(Ch + (size_t)r1 * N + c) = p1;
            } else {
                float2 p0; p0.x = v00; p0.y = v01;
                float2 p1; p1.x = v10; p1.y = v11;
                *(float2*)(C + (size_t)r0 * N + c) = p0;
                *(float2*)(C + (size_t)r1 * N + c) = p1;
            }
        }
    }
}

// ---------------- hgemm64: BM=64, BN=64, BK=32, 128 thr (chip-filling) ----
#define SM_H64 (3 * 2 * 64 * HROW * 2)              // 30720

template <int EPI>
__global__ __launch_bounds__(128)
void hgemm64_k(const __half* __restrict__ A, const __half* __restrict__ B,
               const float* __restrict__ bias, const float* __restrict__ resid,
               float* __restrict__ C, int N, int K) {
    constexpr int BK  = 32;
    constexpr int ASZ = 64 * HROW;

    extern __shared__ __half smem_h[];
    __half* sA = smem_h;
    __half* sB = smem_h + 3 * ASZ;

    const int bm  = blockIdx.x * 64;
    const int bn  = blockIdx.y * 64;
    const int tid = threadIdx.x;
    const int lane = tid & 31;
    const int wid  = tid >> 5;
    const int wm   = (wid & 1) * 32;
    const int wn   = (wid >> 1) * 32;
    const int g    = lane >> 2;
    const int t    = lane & 3;

    float acc[2][4][4];
#pragma unroll
    for (int i = 0; i < 2; i++)
#pragma unroll
        for (int j = 0; j < 4; j++)
#pragma unroll
            for (int r = 0; r < 4; r++) acc[i][j][r] = 0.f;

    const unsigned sAaddr = (unsigned)__cvta_generic_to_shared(sA);
    const unsigned sBaddr = (unsigned)__cvta_generic_to_shared(sB);
    const int ntiles = K / BK;

    auto issue = [&](int st, int kt) {
#pragma unroll
        for (int i = 0; i < 4; i++) {
            int f   = tid + i * 128;                // 0..511
            int isB = f >> 8;
            int row = (f >> 2) & 63;
            int c   = (f & 3) * 8;
            const __half* src = (isB ? B + (size_t)(bn + row) * K
                                     : A + (size_t)(bm + row) * K) + kt * BK + c;
            unsigned dst = (isB ? sBaddr : sAaddr) + (st * ASZ + row * HROW + c) * 2;
            cp16(dst, src, true);
        }
    };

    issue(0, 0); cp_commit();
    issue(1, 1); cp_commit();

    for (int kt = 0; kt < ntiles; kt++) {
        cp_wait1();
        __syncthreads();
        const int cur = kt % 3;
        const __half* As = sA + cur * ASZ;
        const __half* Bs = sB + cur * ASZ;
#pragma unroll
        for (int ks = 0; ks < 2; ks++) {
            const int kk0 = ks * 16;
            unsigned af[2][4], bf[4][2];
#pragma unroll
            for (int i = 0; i < 2; i++) {
                const int mr = wm + i * 16 + g;
                af[i][0] = *(const unsigned*)&As[mr * HROW + kk0 + 2 * t];
                af[i][1] = *(const unsigned*)&As[(mr + 8) * HROW + kk0 + 2 * t];
                af[i][2] = *(const unsigned*)&As[mr * HROW + kk0 + 2 * t + 8];
                af[i][3] = *(const unsigned*)&As[(mr + 8) * HROW + kk0 + 2 * t + 8];
            }
#pragma unroll
            for (int j = 0; j < 4; j++) {
                const int nc = wn + j * 8 + g;
                bf[j][0] = *(const unsigned*)&Bs[nc * HROW + kk0 + 2 * t];
                bf[j][1] = *(const unsigned*)&Bs[nc * HROW + kk0 + 2 * t + 8];
            }
#pragma unroll
            for (int i = 0; i < 2; i++)
#pragma unroll
                for (int j = 0; j < 4; j++)
                    mma_f16(acc[i][j], af[i], bf[j]);
        }
        if (kt + 2 < ntiles) issue((kt + 2) % 3, kt + 2);
        cp_commit();
    }

#pragma unroll
    for (int i = 0; i < 2; i++) {
        const int r0 = bm + wm + i * 16 + g;
        const int r1 = r0 + 8;
#pragma unroll
        for (int j = 0; j < 4; j++) {
            const int c = bn + wn + j * 8 + 2 * t;
            float v00 = acc[i][j][0], v01 = acc[i][j][1];
            float v10 = acc[i][j][2], v11 = acc[i][j][3];
            if (EPI & 1) {
                float bb0 = bias[c], bb1 = bias[c + 1];
                v00 += bb0; v01 += bb1; v10 += bb0; v11 += bb1;
            }
            if (EPI & 2) {
                v00 = gelu_exact(v00); v01 = gelu_exact(v01);
                v10 = gelu_exact(v10); v11 = gelu_exact(v11);
            }
            if (EPI & 4) {
                const float* rp0 = resid + (size_t)r0 * N + c;
                const float* rp1 = resid + (size_t)r1 * N + c;
                v00 += rp0[0]; v01 += rp0[1];
                v10 += rp1[0]; v11 += rp1[1];
            }
            float2 p0; p0.x = v00; p0.y = v01;
            float2 p1; p1.x = v10; p1.y = v11;
            *(float2*)(C + (size_t)r0 * N + c) = p0;
            *(float2*)(C + (size_t)r1 * N + c) = p1;
        }
    }
}

// ---------------- fp16 logits GEMM (unchanged from round 14) ----------------
#define SM_LOGH (3 * 2 * 128 * HROW * 2)            // 61440

__global__ __launch_bounds__(256)
void logits_h_k(const __half* __restrict__ A, const __half* __restrict__ Bm,
                float* __restrict__ C, int N, int K) {
    constexpr int BK  = 32;
    constexpr int ASZ = 128 * HROW;

    extern __shared__ __half smem_h[];
    __half* sA = smem_h;
    __half* sB = smem_h + 3 * ASZ;

    const int bm  = blockIdx.x * 128;
    const int bn  = blockIdx.y * 128;
    const int tid = threadIdx.x;
    const int lane = tid & 31;
    const int wid  = tid >> 5;
    const int wm   = (wid & 3) * 32;
    const int wn   = (wid >> 2) * 64;
    const int g    = lane >> 2;
    const int t    = lane & 3;

    float acc[2][8][4];
#pragma unroll
    for (int i = 0; i < 2; i++)
#pragma unroll
        for (int j = 0; j < 8; j++)
#pragma unroll
            for (int r = 0; r < 4; r++) acc[i][j][r] = 0.f;

    const unsigned sAaddr = (unsigned)__cvta_generic_to_shared(sA);
    const unsigned sBaddr = (unsigned)__cvta_generic_to_shared(sB);
    const int ntiles = K / BK;

    auto issue = [&](int st, int kt) {
#pragma unroll
        for (int i = 0; i < 4; i++) {
            int f   = tid + i * 256;
            int isB = f >> 9;
            int row = (f >> 2) & 127;
            int c   = (f & 3) * 8;
            const __half* src;
            bool pred = true;
            if (isB) {
                int gn = bn + row;
                if (gn >= N) { gn = 0; pred = false; }
                src = Bm + (size_t)gn * K + kt * BK + c;
            } else {
                src = A + (size_t)(bm + row) * K + kt * BK + c;
            }
            unsigned dst = (isB ? sBaddr : sAaddr) + (st * ASZ + row * HROW + c) * 2;
            cp16(dst, src, pred);
        }
    };

    issue(0, 0); cp_commit();
    issue(1, 1); cp_commit();

    for (int kt = 0; kt < ntiles; kt++) {
        cp_wait1();
        __syncthreads();
        const int cur = kt % 3;
        const __half* As = sA + cur * ASZ;
        const __half* Bs = sB + cur * ASZ;
#pragma unroll
        for (int ks = 0; ks < 2; ks++) {
            const int kk0 = ks * 16;
            unsigned af[2][4], bf[8][2];
#pragma unroll
            for (int i = 0; i < 2; i++) {
                const int mr = wm + i * 16 + g;
                af[i][0] = *(const unsigned*)&As[mr * HROW + kk0 + 2 * t];
                af[i][1] = *(const unsigned*)&As[(mr + 8) * HROW + kk0 + 2 * t];
                af[i][2] = *(const unsigned*)&As[mr * HROW + kk0 + 2 * t + 8];
                af[i][3] = *(const unsigned*)&As[(mr + 8) * HROW + kk0 + 2 * t + 8];
            }
#pragma unroll
            for (int j = 0; j < 8; j++) {
                const int nc = wn + j * 8 + g;
                bf[j][0] = *(const unsigned*)&Bs[nc * HROW + kk0 + 2 * t];
                bf[j][1] = *(const unsigned*)&Bs[nc * HROW + kk0 + 2 * t + 8];
            }
#pragma unroll
            for (int i = 0; i < 2; i++)
#pragma unroll
                for (int j = 0; j < 8; j++)
                    mma_f16(acc[i][j], af[i], bf[j]);
        }
        if (kt + 2 < ntiles) issue((kt + 2) % 3, kt + 2);
        cp_commit();
    }

#pragma unroll
    for (int i = 0; i < 2; i++) {
        const int r0 = bm + wm + i * 16 + g;
        const int r1 = r0 + 8;
        float* cp0 = C + (size_t)r0 * N;
        float* cp1 = C + (size_t)r1 * N;
#pragma unroll
        for (int j = 0; j < 8; j++) {
            const int c = bn + wn + j * 8 + 2 * t;
            if (c < N)     { cp0[c]     = acc[i][j][0]; cp1[c]     = acc[i][j][2]; }
            if (c + 1 < N) { cp0[c + 1] = acc[i][j][1]; cp1[c + 1] = acc[i][j][3]; }
        }
    }
}

// ---------------- Causal attention: 64q flash tile (fp32 in, fp16 out) -----
#define ATTN_SMEM (4 * 64 * 68 * 4 + 2 * 64 * 4)

__global__ __launch_bounds__(256)
void attn_kernel(const float* __restrict__ qkv, __half* __restrict__ o) {
    extern __shared__ float sm[];
    float (*Qs)[68] = (float(*)[68])sm;
    float (*Ks)[68] = (float(*)[68])(sm + 64 * 68);
    float (*Vs)[68] = (float(*)[68])(sm + 2 * 64 * 68);
    float (*Ss)[68] = (float(*)[68])(sm + 3 * 64 * 68);
    float* ms = sm + 4 * 64 * 68;
    float* ls = ms + 64;

    const int bh  = blockIdx.y;
    const int b   = bh / H_SZ, h = bh % H_SZ;
    const int q0  = blockIdx.x * 64;
    const int tid = threadIdx.x;
    const int tx  = tid & 15, ty = tid >> 4;

    const float* qb = qkv + h * D_SZ;
    const float* kb = qkv + E_SZ + h * D_SZ;
    const float* vb = qkv + 2 * E_SZ + h * D_SZ;

#pragma unroll
    for (int i = 0; i < 4; i++) {
        int f  = tid + i * 256;
        int qq = f & 63, d4 = (f >> 6) * 4;
        float4 t = *(const float4*)(qb + (size_t)(b * T_SZ + q0 + qq) * QKV_LD + d4);
        Qs[d4+0][qq] = t.x * 0.125f; Qs[d4+1][qq] = t.y * 0.125f;
        Qs[d4+2][qq] = t.z * 0.125f; Qs[d4+3][qq] = t.w * 0.125f;
    }
    if (tid < 64) { ms[tid] = -1e30f; ls[tid] = 0.f; }

    float acc[4][4];
#pragma unroll
    for (int r = 0; r < 4; r++)
#pragma unroll
        for (int c = 0; c < 4; c++) acc[r][c] = 0.f;

    for (int kt = 0; kt <= q0; kt += 64) {
#pragma unroll
        for (int i = 0; i < 4; i++) {
            int f  = tid + i * 256;
            int kk = f & 63, d4 = (f >> 6) * 4;
            float4 t = *(const float4*)(kb + (size_t)(b * T_SZ + kt + kk) * QKV_LD + d4);
            Ks[d4+0][kk] = t.x; Ks[d4+1][kk] = t.y;
            Ks[d4+2][kk] = t.z; Ks[d4+3][kk] = t.w;
        }
#pragma unroll
        for (int i = 0; i < 4; i++) {
            int f  = tid + i * 256;
            int kk = f >> 4, d4 = (f & 15) * 4;
            *(float4*)&Vs[kk][d4] =
                *(const float4*)(vb + (size_t)(b * T_SZ + kt + kk) * QKV_LD + d4);
        }
        __syncthreads();

        float s[4][4];
#pragma unroll
        for (int r = 0; r < 4; r++)
#pragma unroll
            for (int c = 0; c < 4; c++) s[r][c] = 0.f;
#pragma unroll 4
        for (int d = 0; d < 64; d++) {
            float4 aq = *(const float4*)&Qs[d][4 * ty];
            float4 bk = *(const float4*)&Ks[d][4 * tx];
            float a[4] = {aq.x, aq.y, aq.z, aq.w};
            float bb[4] = {bk.x, bk.y, bk.z, bk.w};
#pragma unroll
            for (int r = 0; r < 4; r++)
#pragma unroll
                for (int c = 0; c < 4; c++) s[r][c] += a[r] * bb[c];
        }

        const bool diag = (kt == q0);
        float cfl[4];
#pragma unroll
        for (int r = 0; r < 4; r++) {
            const int row = 4 * ty + r;
            if (diag) {
#pragma unroll
                for (int c = 0; c < 4; c++)
                    if (4 * tx + c > row) s[r][c] = -1e30f;
            }
            float mx = fmaxf(fmaxf(s[r][0], s[r][1]), fmaxf(s[r][2], s[r][3]));
#pragma unroll
            for (int off = 1; off < 16; off <<= 1)
                mx = fmaxf(mx, __shfl_xor_sync(0xffffffffu, mx, off));
            const float mold = ms[row];
            const float mnew = fmaxf(mold, mx);
            float ps = 0.f;
#pragma unroll
            for (int c = 0; c < 4; c++) {
                float p = __expf(s[r][c] - mnew);
                Ss[row][4 * tx + c] = p;
                ps += p;
            }
#pragma unroll
            for (int off = 1; off < 16; off <<= 1)
                ps += __shfl_xor_sync(0xffffffffu, ps, off);
            cfl[r] = __expf(mold - mnew);
            if (tx == 0) { ms[row] = mnew; ls[row] = ls[row] * cfl[r] + ps; }
        }
        __syncwarp();

#pragma unroll
        for (int r = 0; r < 4; r++)
#pragma unroll
            for (int c = 0; c < 4; c++) acc[r][c] *= cfl[r];
#pragma unroll 4
        for (int kk = 0; kk < 64; kk++) {
            float4 vv = *(const float4*)&Vs[kk][4 * tx];
#pragma unroll
            for (int r = 0; r < 4; r++) {
                float p = Ss[4 * ty + r][kk];
                acc[r][0] += p * vv.x; acc[r][1] += p * vv.y;
                acc[r][2] += p * vv.z; acc[r][3] += p * vv.w;
            }
        }
        __syncthreads();
    }

#pragma unroll
    for (int r = 0; r < 4; r++) {
        const float inv = 1.f / ls[4 * ty + r];
        __half2 h01 = __floats2half2_rn(acc[r][0] * inv, acc[r][1] * inv);
        __half2 h23 = __floats2half2_rn(acc[r][2] * inv, acc[r][3] * inv);
        uint2 u;
        u.x = *(unsigned*)&h01;
        u.y = *(unsigned*)&h23;
        *(uint2*)(o + (size_t)(b * T_SZ + q0 + 4 * ty + r) * E_SZ + h * D_SZ + 4 * tx) = u;
    }
}

// ---------------- Host orchestration ----------------
extern "C" void kernel_launch(void* const* d_in, const int* in_sizes, int n_in,
                              void* d_out, int out_size) {
    (void)in_sizes; (void)n_in; (void)out_size;
    const int*   tokens = (const int*)  d_in[0];
    const float* wte    = (const float*)d_in[1];
    const float* wpe    = (const float*)d_in[2];
    const float* Wq     = (const float*)d_in[3];
    const float* Wk     = (const float*)d_in[4];
    const float* Wv     = (const float*)d_in[5];
    const float* Wo     = (const float*)d_in[6];
    const float* bo     = (const float*)d_in[7];
    const float* ln1_s  = (const float*)d_in[8];
    const float* ln1_b  = (const float*)d_in[9];
    const float* W1     = (const float*)d_in[10];
    const float* b1     = (const float*)d_in[11];
    const float* W2     = (const float*)d_in[12];
    const float* b2     = (const float*)d_in[13];
    const float* ln2_s  = (const float*)d_in[14];
    const float* ln2_b  = (const float*)d_in[15];
    const float* lnf_s  = (const float*)d_in[16];
    const float* lnf_b  = (const float*)d_in[17];
    float* out = (float*)d_out;

    float *x, *qkv;
    __half *hh, *atth, *m1h, *wqkvT, *woT, *w1T, *w2T, *wteh;
    cudaGetSymbolAddress((void**)&x,     g_x);
    cudaGetSymbolAddress((void**)&hh,    g_hh);
    cudaGetSymbolAddress((void**)&qkv,   g_qkv);
    cudaGetSymbolAddress((void**)&atth,  g_atth);
    cudaGetSymbolAddress((void**)&m1h,   g_m1h);
    cudaGetSymbolAddress((void**)&wqkvT, g_wqkvT);
    cudaGetSymbolAddress((void**)&woT,   g_woT);
    cudaGetSymbolAddress((void**)&w1T,   g_w1T);
    cudaGetSymbolAddress((void**)&w2T,   g_w2T);
    cudaGetSymbolAddress((void**)&wteh,  g_wteh);

    cudaFuncSetAttribute(attn_kernel,
                         cudaFuncAttributeMaxDynamicSharedMemorySize, ATTN_SMEM);
    cudaFuncSetAttribute(hgemm_k<0, false>,
                         cudaFuncAttributeMaxDynamicSharedMemorySize, SM_H128);
    cudaFuncSetAttribute(hgemm_k<3, true>,
                         cudaFuncAttributeMaxDynamicSharedMemorySize, SM_H128);
    cudaFuncSetAttribute(hgemm64_k<5>,
                         cudaFuncAttributeMaxDynamicSharedMemorySize, SM_H64);
    cudaFuncSetAttribute(logits_h_k,
                         cudaFuncAttributeMaxDynamicSharedMemorySize, SM_LOGH);

    // ---- per-launch weight transpose+convert to fp16 [N][K] ----
    {
        const dim3 trb(32, 8);
        const size_t sE = (size_t)E_SZ * E_SZ;
        const size_t sQ = (size_t)QKV_LD * E_SZ;
        const size_t sF = (size_t)E_SZ * FF;
        // Wq|Wk|Wv -> wqkvT [2304][768]
        tr_half_kernel<<<dim3(24, 24, L_SZ), trb>>>(Wq, wqkvT,              E_SZ, E_SZ, sE, sQ);
        tr_half_kernel<<<dim3(24, 24, L_SZ), trb>>>(Wk, wqkvT + sE,         E_SZ, E_SZ, sE, sQ);
        tr_half_kernel<<<dim3(24, 24, L_SZ), trb>>>(Wv, wqkvT + 2 * sE,     E_SZ, E_SZ, sE, sQ);
        tr_half_kernel<<<dim3(24, 24, L_SZ), trb>>>(Wo, woT,                E_SZ, E_SZ, sE, sE);
        tr_half_kernel<<<dim3(96, 24, L_SZ), trb>>>(W1, w1T,                E_SZ, FF,   sF, sF);
        tr_half_kernel<<<dim3(24, 96, L_SZ), trb>>>(W2, w2T,                FF,   E_SZ, sF, sF);
        const int nV = V_SZ * E_SZ / 4;
        cvt_half_kernel<<<(nV + 255) / 256, 256>>>((const float4*)wte, (uint2*)wteh, nV);
    }

    embed_kernel<<<BT, 192>>>(tokens, wte, wpe, x);

    const dim3 gQKV(BT / 128, QKV_LD / 128);       // 16 x 18
    const dim3 gF(BT / 128, FF / 128);             // 16 x 24
    const dim3 gE64(BT / 64, E_SZ / 64);           // 32 x 12
    const dim3 gATT(T_SZ / 64, B_SZ * H_SZ);       // 16 x 24
    const dim3 gLOG(BT / 128, (V_SZ + 127) / 128); // 16 x 393

    for (int l = 0; l < L_SZ; l++) {
        const size_t wqOff = (size_t)l * QKV_LD * E_SZ;
        const size_t wOff  = (size_t)l * E_SZ * E_SZ;
        const size_t w1Off = (size_t)l * FF * E_SZ;
        const size_t vOff  = (size_t)l * E_SZ;
        const size_t fOff  = (size_t)l * FF;

        layernorm_kernel<<<BT, 256>>>(x, ln1_s + vOff, ln1_b + vOff, hh);
        hgemm_k<0, false><<<gQKV, 256, SM_H128>>>(hh, wqkvT + wqOff, nullptr, nullptr,
                                                  qkv, nullptr, QKV_LD, E_SZ);
        attn_kernel<<<gATT, 256, ATTN_SMEM>>>(qkv, atth);
        hgemm64_k<5><<<gE64, 128, SM_H64>>>(atth, woT + wOff, bo + vOff, x, x, E_SZ, E_SZ);
        layernorm_kernel<<<BT, 256>>>(x, ln2_s + vOff, ln2_b + vOff, hh);
        hgemm_k<3, true><<<gF, 256, SM_H128>>>(hh, w1T + w1Off, b1 + fOff, nullptr,
                                               nullptr, m1h, FF, E_SZ);
        hgemm64_k<5><<<gE64, 128, SM_H64>>>(m1h, w2T + w1Off, b2 + vOff, x, x, E_SZ, FF);
    }

    layernorm_kernel<<<BT, 256>>>(x, lnf_s, lnf_b, hh);
    logits_h_k<<<gLOG, 256, SM_LOGH>>>(hh, wteh, out, V_SZ, E_SZ);
}

// round 16
// speedup vs baseline: 1.5572x; 1.0005x over previous
#include <cuda_runtime.h>
#include <cuda_fp16.h>
#include <math.h>
#include <stdint.h>

// ---------------- Problem constants ----------------
#define V_SZ 50257
#define E_SZ 768
#define H_SZ 12
#define L_SZ 6
#define T_SZ 1024
#define B_SZ 2
#define D_SZ 64
#define BT   (B_SZ * T_SZ)      // 2048
#define FF   (4 * E_SZ)         // 3072
#define QKV_LD (3 * E_SZ)       // 2304

// ---------------- Scratch ----------------
__device__ float  g_x    [BT * E_SZ];
__device__ __half g_hh   [BT * E_SZ];      // LN outputs (half)
__device__ float  g_qkv  [BT * QKV_LD];
__device__ __half g_atth [BT * E_SZ];
__device__ __half g_m1h  [BT * FF];
// transposed fp16 weights: [N][K]
__device__ __half g_wqkvT[L_SZ * QKV_LD * E_SZ];
__device__ __half g_woT  [L_SZ * E_SZ * E_SZ];
__device__ __half g_w1T  [L_SZ * FF * E_SZ];
__device__ __half g_w2T  [L_SZ * E_SZ * FF];
__device__ __half g_wteh [V_SZ * E_SZ];

// ---------------- converts ----------------
// fp32 -> fp16 (rn), 4 elems/thread (no transpose; for wte)
__global__ void cvt_half_kernel(const float4* __restrict__ src, uint2* __restrict__ dst, int n4) {
    int i = blockIdx.x * 256 + threadIdx.x;
    if (i >= n4) return;
    float4 v = src[i];
    __half2 h0 = __floats2half2_rn(v.x, v.y);
    __half2 h1 = __floats2half2_rn(v.z, v.w);
    uint2 u;
    u.x = *(unsigned*)&h0;
    u.y = *(unsigned*)&h1;
    dst[i] = u;
}

// transpose-convert: src [K][N] fp32 -> dst [N][K] half.  block 32x8, grid (N/32, K/32, L)
__global__ void tr_half_kernel(const float* __restrict__ src, __half* __restrict__ dst,
                               int K, int N, size_t srcLS, size_t dstLS) {
    __shared__ float tile[32][33];
    const float* s = src + blockIdx.z * srcLS;
    __half* d = dst + blockIdx.z * dstLS;
    int n0 = blockIdx.x * 32, k0 = blockIdx.y * 32;
    int tx = threadIdx.x, ty = threadIdx.y;
#pragma unroll
    for (int j = 0; j < 4; j++)
        tile[ty + j * 8][tx] = s[(size_t)(k0 + ty + j * 8) * N + n0 + tx];
    __syncthreads();
#pragma unroll
    for (int j = 0; j < 4; j++)
        d[(size_t)(n0 + ty + j * 8) * K + k0 + tx] = __float2half_rn(tile[tx][ty + j * 8]);
}

// ---------------- Embedding ----------------
__global__ void embed_kernel(const int* __restrict__ tok,
                             const float* __restrict__ wte,
                             const float* __restrict__ wpe,
                             float* __restrict__ x) {
    int row = blockIdx.x;
    int t   = row % T_SZ;
    int tk  = tok[row];
    int e   = threadIdx.x * 4;
    const float4 a = *(const float4*)(wte + (size_t)tk * E_SZ + e);
    const float4 b = *(const float4*)(wpe + (size_t)t  * E_SZ + e);
    float4 o;
    o.x = a.x + b.x; o.y = a.y + b.y; o.z = a.z + b.z; o.w = a.w + b.w;
    *(float4*)(x + (size_t)row * E_SZ + e) = o;
}

// ---------------- LayerNorm: fp32 in -> fp16 out ----------------
__global__ void layernorm_kernel(const float* __restrict__ x,
                                 const float* __restrict__ sc,
                                 const float* __restrict__ bi,
                                 __half* __restrict__ out) {
    int row = blockIdx.x;
    const float* xr = x + (size_t)row * E_SZ;
    float lv[3];
    float s = 0.f, sq = 0.f;
#pragma unroll
    for (int i = 0; i < 3; i++) {
        float t = xr[threadIdx.x + i * 256];
        lv[i] = t; s += t; sq += t * t;
    }
#pragma unroll
    for (int o = 16; o > 0; o >>= 1) {
        s  += __shfl_down_sync(0xffffffffu, s,  o);
        sq += __shfl_down_sync(0xffffffffu, sq, o);
    }
    __shared__ float sa[8], sb[8];
    int w = threadIdx.x >> 5, lane = threadIdx.x & 31;
    if (lane == 0) { sa[w] = s; sb[w] = sq; }
    __syncthreads();
    __shared__ float s_mu, s_rstd;
    if (threadIdx.x == 0) {
        float ts = 0.f, tq = 0.f;
#pragma unroll
        for (int i = 0; i < 8; i++) { ts += sa[i]; tq += sb[i]; }
        float mu  = ts * (1.0f / E_SZ);
        float var = tq * (1.0f / E_SZ) - mu * mu;
        s_mu = mu;
        s_rstd = rsqrtf(var + 1e-5f);
    }
    __syncthreads();
    float mu = s_mu, rstd = s_rstd;
#pragma unroll
    for (int i = 0; i < 3; i++) {
        int c = threadIdx.x + i * 256;
        out[(size_t)row * E_SZ + c] = __float2half_rn((lv[i] - mu) * rstd * sc[c] + bi[c]);
    }
}

// ---------------- cp.async helpers ----------------
__device__ __forceinline__ void cp16(unsigned sdst, const void* src, bool pred) {
    int sz = pred ? 16 : 0;
    asm volatile("cp.async.cg.shared.global [%0], [%1], 16, %2;\n"
                 :: "r"(sdst), "l"(src), "r"(sz));
}
__device__ __forceinline__ void cp_commit() {
    asm volatile("cp.async.commit_group;\n");
}
__device__ __forceinline__ void cp_wait1() {
    asm volatile("cp.async.wait_group 1;\n");
}

__device__ __forceinline__ float gelu_exact(float v) {
    return 0.5f * v * (1.0f + erff(v * 0.70710678118654752f));
}
__device__ __forceinline__ void mma_f16(float* d, const unsigned* a, const unsigned* b) {
    asm volatile(
        "mma.sync.aligned.m16n8k16.row.col.f32.f16.f16.f32 "
        "{%0,%1,%2,%3}, {%4,%5,%6,%7}, {%8,%9}, {%0,%1,%2,%3};"
        : "+f"(d[0]), "+f"(d[1]), "+f"(d[2]), "+f"(d[3])
        : "r"(a[0]), "r"(a[1]), "r"(a[2]), "r"(a[3]), "r"(b[0]), "r"(b[1]));
}

#define HROW 40                                     // halfs per smem row (32 + 8 pad)

// ---------------- hgemm: BM=128, BN=128, BK=32, 256 thr ----------------
// C[M,N] = A[M,K](half) @ B[N,K](half)^T, fp32 acc.
// EPI: 1=+bias, 2=GELU, 4=+resid(fp32).  OUTH: write half to Ch else fp32 to C.
#define SM_H128 (3 * 2 * 128 * HROW * 2)            // 61440

template <int EPI, bool OUTH>
__global__ __launch_bounds__(256)
void hgemm_k(const __half* __restrict__ A, const __half* __restrict__ B,
             const float* __restrict__ bias, const float* __restrict__ resid,
             float* __restrict__ C, __half* __restrict__ Ch, int N, int K) {
    constexpr int BK  = 32;
    constexpr int ASZ = 128 * HROW;

    extern __shared__ __half smem_h[];
    __half* sA = smem_h;
    __half* sB = smem_h + 3 * ASZ;

    const int bm  = blockIdx.x * 128;
    const int bn  = blockIdx.y * 128;
    const int tid = threadIdx.x;
    const int lane = tid & 31;
    const int wid  = tid >> 5;
    const int wm   = (wid & 3) * 32;
    const int wn   = (wid >> 2) * 64;
    const int g    = lane >> 2;
    const int t    = lane & 3;

    float acc[2][8][4];
#pragma unroll
    for (int i = 0; i < 2; i++)
#pragma unroll
        for (int j = 0; j < 8; j++)
#pragma unroll
            for (int r = 0; r < 4; r++) acc[i][j][r] = 0.f;

    const unsigned sAaddr = (unsigned)__cvta_generic_to_shared(sA);
    const unsigned sBaddr = (unsigned)__cvta_generic_to_shared(sB);
    const int ntiles = K / BK;

    auto issue = [&](int st, int kt) {
#pragma unroll
        for (int i = 0; i < 4; i++) {
            int f   = tid + i * 256;
            int isB = f >> 9;
            int row = (f >> 2) & 127;
            int c   = (f & 3) * 8;
            const __half* src = (isB ? B + (size_t)(bn + row) * K
                                     : A + (size_t)(bm + row) * K) + kt * BK + c;
            unsigned dst = (isB ? sBaddr : sAaddr) + (st * ASZ + row * HROW + c) * 2;
            cp16(dst, src, true);
        }
    };

    issue(0, 0); cp_commit();
    issue(1, 1); cp_commit();

    for (int kt = 0; kt < ntiles; kt++) {
        cp_wait1();
        __syncthreads();
        const int cur = kt % 3;
        const __half* As = sA + cur * ASZ;
        const __half* Bs = sB + cur * ASZ;
#pragma unroll
        for (int ks = 0; ks < 2; ks++) {
            const int kk0 = ks * 16;
            unsigned af[2][4], bf[8][2];
#pragma unroll
            for (int i = 0; i < 2; i++) {
                const int mr = wm + i * 16 + g;
                af[i][0] = *(const unsigned*)&As[mr * HROW + kk0 + 2 * t];
                af[i][1] = *(const unsigned*)&As[(mr + 8) * HROW + kk0 + 2 * t];
                af[i][2] = *(const unsigned*)&As[mr * HROW + kk0 + 2 * t + 8];
                af[i][3] = *(const unsigned*)&As[(mr + 8) * HROW + kk0 + 2 * t + 8];
            }
#pragma unroll
            for (int j = 0; j < 8; j++) {
                const int nc = wn + j * 8 + g;
                bf[j][0] = *(const unsigned*)&Bs[nc * HROW + kk0 + 2 * t];
                bf[j][1] = *(const unsigned*)&Bs[nc * HROW + kk0 + 2 * t + 8];
            }
#pragma unroll
            for (int i = 0; i < 2; i++)
#pragma unroll
                for (int j = 0; j < 8; j++)
                    mma_f16(acc[i][j], af[i], bf[j]);
        }
        if (kt + 2 < ntiles) issue((kt + 2) % 3, kt + 2);
        cp_commit();
    }

#pragma unroll
    for (int i = 0; i < 2; i++) {
        const int r0 = bm + wm + i * 16 + g;
        const int r1 = r0 + 8;
#pragma unroll
        for (int j = 0; j < 8; j++) {
            const int c = bn + wn + j * 8 + 2 * t;
            float v00 = acc[i][j][0], v01 = acc[i][j][1];
            float v10 = acc[i][j][2], v11 = acc[i][j][3];
            if (EPI & 1) {
                float bb0 = bias[c], bb1 = bias[c + 1];
                v00 += bb0; v01 += bb1; v10 += bb0; v11 += bb1;
            }
            if (EPI & 2) {
                v00 = gelu_exact(v00); v01 = gelu_exact(v01);
                v10 = gelu_exact(v10); v11 = gelu_exact(v11);
            }
            if (EPI & 4) {
                const float* rp0 = resid + (size_t)r0 * N + c;
                const float* rp1 = resid + (size_t)r1 * N + c;
                v00 += rp0[0]; v01 += rp0[1];
                v10 += rp1[0]; v11 += rp1[1];
            }
            if (OUTH) {
                __half2 p0 = __floats2half2_rn(v00, v01);
                __half2 p1 = __floats2half2_rn(v10, v11);
                *(__half2*)(Ch + (size_t)r0 * N + c) = p0;
                *(__half2*)(Ch + (size_t)r1 * N + c) = p1;
            } else {
                float2 p0; p0.x = v00; p0.y = v01;
                float2 p1; p1.x = v10; p1.y = v11;
                *(float2*)(C + (size_t)r0 * N + c) = p0;
                *(float2*)(C + (size_t)r1 * N + c) = p1;
            }
        }
    }
}

// ---------------- hgemm64: BM=64, BN=64, BK=32, 128 thr (chip-filling) ----
#define SM_H64 (3 * 2 * 64 * HROW * 2)              // 30720

template <int EPI>
__global__ __launch_bounds__(128)
void hgemm64_k(const __half* __restrict__ A, const __half* __restrict__ B,
               const float* __restrict__ bias, const float* __restrict__ resid,
               float* __restrict__ C, int N, int K) {
    constexpr int BK  = 32;
    constexpr int ASZ = 64 * HROW;

    extern __shared__ __half smem_h[];
    __half* sA = smem_h;
    __half* sB = smem_h + 3 * ASZ;

    const int bm  = blockIdx.x * 64;
    const int bn  = blockIdx.y * 64;
    const int tid = threadIdx.x;
    const int lane = tid & 31;
    const int wid  = tid >> 5;
    const int wm   = (wid & 1) * 32;
    const int wn   = (wid >> 1) * 32;
    const int g    = lane >> 2;
    const int t    = lane & 3;

    float acc[2][4][4];
#pragma unroll
    for (int i = 0; i < 2; i++)
#pragma unroll
        for (int j = 0; j < 4; j++)
#pragma unroll
            for (int r = 0; r < 4; r++) acc[i][j][r] = 0.f;

    const unsigned sAaddr = (unsigned)__cvta_generic_to_shared(sA);
    const unsigned sBaddr = (unsigned)__cvta_generic_to_shared(sB);
    const int ntiles = K / BK;

    auto issue = [&](int st, int kt) {
#pragma unroll
        for (int i = 0; i < 4; i++) {
            int f   = tid + i * 128;                // 0..511
            int isB = f >> 8;
            int row = (f >> 2) & 63;
            int c   = (f & 3) * 8;
            const __half* src = (isB ? B + (size_t)(bn + row) * K
                                     : A + (size_t)(bm + row) * K) + kt * BK + c;
            unsigned dst = (isB ? sBaddr : sAaddr) + (st * ASZ + row * HROW + c) * 2;
            cp16(dst, src, true);
        }
    };

    issue(0, 0); cp_commit();
    issue(1, 1); cp_commit();

    for (int kt = 0; kt < ntiles; kt++) {
        cp_wait1();
        __syncthreads();
        const int cur = kt % 3;
        const __half* As = sA + cur * ASZ;
        const __half* Bs = sB + cur * ASZ;
#pragma unroll
        for (int ks = 0; ks < 2; ks++) {
            const int kk0 = ks * 16;
            unsigned af[2][4], bf[4][2];
#pragma unroll
            for (int i = 0; i < 2; i++) {
                const int mr = wm + i * 16 + g;
                af[i][0] = *(const unsigned*)&As[mr * HROW + kk0 + 2 * t];
                af[i][1] = *(const unsigned*)&As[(mr + 8) * HROW + kk0 + 2 * t];
                af[i][2] = *(const unsigned*)&As[mr * HROW + kk0 + 2 * t + 8];
                af[i][3] = *(const unsigned*)&As[(mr + 8) * HROW + kk0 + 2 * t + 8];
            }
#pragma unroll
            for (int j = 0; j < 4; j++) {
                const int nc = wn + j * 8 + g;
                bf[j][0] = *(const unsigned*)&Bs[nc * HROW + kk0 + 2 * t];
                bf[j][1] = *(const unsigned*)&Bs[nc * HROW + kk0 + 2 * t + 8];
            }
#pragma unroll
            for (int i = 0; i < 2; i++)
#pragma unroll
                for (int j = 0; j < 4; j++)
                    mma_f16(acc[i][j], af[i], bf[j]);
        }
        if (kt + 2 < ntiles) issue((kt + 2) % 3, kt + 2);
        cp_commit();
    }

#pragma unroll
    for (int i = 0; i < 2; i++) {
        const int r0 = bm + wm + i * 16 + g;
        const int r1 = r0 + 8;
#pragma unroll
        for (int j = 0; j < 4; j++) {
            const int c = bn + wn + j * 8 + 2 * t;
            float v00 = acc[i][j][0], v01 = acc[i][j][1];
            float v10 = acc[i][j][2], v11 = acc[i][j][3];
            if (EPI & 1) {
                float bb0 = bias[c], bb1 = bias[c + 1];
                v00 += bb0; v01 += bb1; v10 += bb0; v11 += bb1;
            }
            if (EPI & 2) {
                v00 = gelu_exact(v00); v01 = gelu_exact(v01);
                v10 = gelu_exact(v10); v11 = gelu_exact(v11);
            }
            if (EPI & 4) {
                const float* rp0 = resid + (size_t)r0 * N + c;
                const float* rp1 = resid + (size_t)r1 * N + c;
                v00 += rp0[0]; v01 += rp0[1];
                v10 += rp1[0]; v11 += rp1[1];
            }
            float2 p0; p0.x = v00; p0.y = v01;
            float2 p1; p1.x = v10; p1.y = v11;
            *(float2*)(C + (size_t)r0 * N + c) = p0;
            *(float2*)(C + (size_t)r1 * N + c) = p1;
        }
    }
}

// ---------------- fp16 logits GEMM (unchanged from round 14) ----------------
#define SM_LOGH (3 * 2 * 128 * HROW * 2)            // 61440

__global__ __launch_bounds__(256)
void logits_h_k(const __half* __restrict__ A, const __half* __restrict__ Bm,
                float* __restrict__ C, int N, int K) {
    constexpr int BK  = 32;
    constexpr int ASZ = 128 * HROW;

    extern __shared__ __half smem_h[];
    __half* sA = smem_h;
    __half* sB = smem_h + 3 * ASZ;

    const int bm  = blockIdx.x * 128;
    const int bn  = blockIdx.y * 128;
    const int tid = threadIdx.x;
    const int lane = tid & 31;
    const int wid  = tid >> 5;
    const int wm   = (wid & 3) * 32;
    const int wn   = (wid >> 2) * 64;
    const int g    = lane >> 2;
    const int t    = lane & 3;

    float acc[2][8][4];
#pragma unroll
    for (int i = 0; i < 2; i++)
#pragma unroll
        for (int j = 0; j < 8; j++)
#pragma unroll
            for (int r = 0; r < 4; r++) acc[i][j][r] = 0.f;

    const unsigned sAaddr = (unsigned)__cvta_generic_to_shared(sA);
    const unsigned sBaddr = (unsigned)__cvta_generic_to_shared(sB);
    const int ntiles = K / BK;

    auto issue = [&](int st, int kt) {
#pragma unroll
        for (int i = 0; i < 4; i++) {
            int f   = tid + i * 256;
            int isB = f >> 9;
            int row = (f >> 2) & 127;
            int c   = (f & 3) * 8;
            const __half* src;
            bool pred = true;
            if (isB) {
                int gn = bn + row;
                if (gn >= N) { gn = 0; pred = false; }
                src = Bm + (size_t)gn * K + kt * BK + c;
            } else {
                src = A + (size_t)(bm + row) * K + kt * BK + c;
            }
            unsigned dst = (isB ? sBaddr : sAaddr) + (st * ASZ + row * HROW + c) * 2;
            cp16(dst, src, pred);
        }
    };

    issue(0, 0); cp_commit();
    issue(1, 1); cp_commit();

    for (int kt = 0; kt < ntiles; kt++) {
        cp_wait1();
        __syncthreads();
        const int cur = kt % 3;
        const __half* As = sA + cur * ASZ;
        const __half* Bs = sB + cur * ASZ;
#pragma unroll
        for (int ks = 0; ks < 2; ks++) {
            const int kk0 = ks * 16;
            unsigned af[2][4], bf[8][2];
#pragma unroll
            for (int i = 0; i < 2; i++) {
                const int mr = wm + i * 16 + g;
                af[i][0] = *(const unsigned*)&As[mr * HROW + kk0 + 2 * t];
                af[i][1] = *(const unsigned*)&As[(mr + 8) * HROW + kk0 + 2 * t];
                af[i][2] = *(const unsigned*)&As[mr * HROW + kk0 + 2 * t + 8];
                af[i][3] = *(const unsigned*)&As[(mr + 8) * HROW + kk0 + 2 * t + 8];
            }
#pragma unroll
            for (int j = 0; j < 8; j++) {
                const int nc = wn + j * 8 + g;
                bf[j][0] = *(const unsigned*)&Bs[nc * HROW + kk0 + 2 * t];
                bf[j][1] = *(const unsigned*)&Bs[nc * HROW + kk0 + 2 * t + 8];
            }
#pragma unroll
            for (int i = 0; i < 2; i++)
#pragma unroll
                for (int j = 0; j < 8; j++)
                    mma_f16(acc[i][j], af[i], bf[j]);
        }
        if (kt + 2 < ntiles) issue((kt + 2) % 3, kt + 2);
        cp_commit();
    }

#pragma unroll
    for (int i = 0; i < 2; i++) {
        const int r0 = bm + wm + i * 16 + g;
        const int r1 = r0 + 8;
        float* cp0 = C + (size_t)r0 * N;
        float* cp1 = C + (size_t)r1 * N;
#pragma unroll
        for (int j = 0; j < 8; j++) {
            const int c = bn + wn + j * 8 + 2 * t;
            if (c < N)     { cp0[c]     = acc[i][j][0]; cp1[c]     = acc[i][j][2]; }
            if (c + 1 < N) { cp0[c + 1] = acc[i][j][1]; cp1[c + 1] = acc[i][j][3]; }
        }
    }
}

// ---------------- Causal attention: 64q flash tile (fp32 in, fp16 out) -----
#define ATTN_SMEM (4 * 64 * 68 * 4 + 2 * 64 * 4)

__global__ __launch_bounds__(256)
void attn_kernel(const float* __restrict__ qkv, __half* __restrict__ o) {
    extern __shared__ float sm[];
    float (*Qs)[68] = (float(*)[68])sm;
    float (*Ks)[68] = (float(*)[68])(sm + 64 * 68);
    float (*Vs)[68] = (float(*)[68])(sm + 2 * 64 * 68);
    float (*Ss)[68] = (float(*)[68])(sm + 3 * 64 * 68);
    float* ms = sm + 4 * 64 * 68;
    float* ls = ms + 64;

    const int bh  = blockIdx.y;
    const int b   = bh / H_SZ, h = bh % H_SZ;
    const int q0  = blockIdx.x * 64;
    const int tid = threadIdx.x;
    const int tx  = tid & 15, ty = tid >> 4;

    const float* qb = qkv + h * D_SZ;
    const float* kb = qkv + E_SZ + h * D_SZ;
    const float* vb = qkv + 2 * E_SZ + h * D_SZ;

#pragma unroll
    for (int i = 0; i < 4; i++) {
        int f  = tid + i * 256;
        int qq = f & 63, d4 = (f >> 6) * 4;
        float4 t = *(const float4*)(qb + (size_t)(b * T_SZ + q0 + qq) * QKV_LD + d4);
        Qs[d4+0][qq] = t.x * 0.125f; Qs[d4+1][qq] = t.y * 0.125f;
        Qs[d4+2][qq] = t.z * 0.125f; Qs[d4+3][qq] = t.w * 0.125f;
    }
    if (tid < 64) { ms[tid] = -1e30f; ls[tid] = 0.f; }

    float acc[4][4];
#pragma unroll
    for (int r = 0; r < 4; r++)
#pragma unroll
        for (int c = 0; c < 4; c++) acc[r][c] = 0.f;

    for (int kt = 0; kt <= q0; kt += 64) {
#pragma unroll
        for (int i = 0; i < 4; i++) {
            int f  = tid + i * 256;
            int kk = f & 63, d4 = (f >> 6) * 4;
            float4 t = *(const float4*)(kb + (size_t)(b * T_SZ + kt + kk) * QKV_LD + d4);
            Ks[d4+0][kk] = t.x; Ks[d4+1][kk] = t.y;
            Ks[d4+2][kk] = t.z; Ks[d4+3][kk] = t.w;
        }
#pragma unroll
        for (int i = 0; i < 4; i++) {
            int f  = tid + i * 256;
            int kk = f >> 4, d4 = (f & 15) * 4;
            *(float4*)&Vs[kk][d4] =
                *(const float4*)(vb + (size_t)(b * T_SZ + kt + kk) * QKV_LD + d4);
        }
        __syncthreads();

        float s[4][4];
#pragma unroll
        for (int r = 0; r < 4; r++)
#pragma unroll
            for (int c = 0; c < 4; c++) s[r][c] = 0.f;
#pragma unroll 4
        for (int d = 0; d < 64; d++) {
            float4 aq = *(const float4*)&Qs[d][4 * ty];
            float4 bk = *(const float4*)&Ks[d][4 * tx];
            float a[4] = {aq.x, aq.y, aq.z, aq.w};
            float bb[4] = {bk.x, bk.y, bk.z, bk.w};
#pragma unroll
            for (int r = 0; r < 4; r++)
#pragma unroll
                for (int c = 0; c < 4; c++) s[r][c] += a[r] * bb[c];
        }

        const bool diag = (kt == q0);
        float cfl[4];
#pragma unroll
        for (int r = 0; r < 4; r++) {
            const int row = 4 * ty + r;
            if (diag) {
#pragma unroll
                for (int c = 0; c < 4; c++)
                    if (4 * tx + c > row) s[r][c] = -1e30f;
            }
            float mx = fmaxf(fmaxf(s[r][0], s[r][1]), fmaxf(s[r][2], s[r][3]));
#pragma unroll
            for (int off = 1; off < 16; off <<= 1)
                mx = fmaxf(mx, __shfl_xor_sync(0xffffffffu, mx, off));
            const float mold = ms[row];
            const float mnew = fmaxf(mold, mx);
            float ps = 0.f;
#pragma unroll
            for (int c = 0; c < 4; c++) {
                float p = __expf(s[r][c] - mnew);
                Ss[row][4 * tx + c] = p;
                ps += p;
            }
#pragma unroll
            for (int off = 1; off < 16; off <<= 1)
                ps += __shfl_xor_sync(0xffffffffu, ps, off);
            cfl[r] = __expf(mold - mnew);
            if (tx == 0) { ms[row] = mnew; ls[row] = ls[row] * cfl[r] + ps; }
        }
        __syncwarp();

#pragma unroll
        for (int r = 0; r < 4; r++)
#pragma unroll
            for (int c = 0; c < 4; c++) acc[r][c] *= cfl[r];
#pragma unroll 4
        for (int kk = 0; kk < 64; kk++) {
            float4 vv = *(const float4*)&Vs[kk][4 * tx];
#pragma unroll
            for (int r = 0; r < 4; r++) {
                float p = Ss[4 * ty + r][kk];
                acc[r][0] += p * vv.x; acc[r][1] += p * vv.y;
                acc[r][2] += p * vv.z; acc[r][3] += p * vv.w;
            }
        }
        __syncthreads();
    }

#pragma unroll
    for (int r = 0; r < 4; r++) {
        const float inv = 1.f / ls[4 * ty + r];
        __half2 h01 = __floats2half2_rn(acc[r][0] * inv, acc[r][1] * inv);
        __half2 h23 = __floats2half2_rn(acc[r][2] * inv, acc[r][3] * inv);
        uint2 u;
        u.x = *(unsigned*)&h01;
        u.y = *(unsigned*)&h23;
        *(uint2*)(o + (size_t)(b * T_SZ + q0 + 4 * ty + r) * E_SZ + h * D_SZ + 4 * tx) = u;
    }
}

// ---------------- Host orchestration ----------------
extern "C" void kernel_launch(void* const* d_in, const int* in_sizes, int n_in,
                              void* d_out, int out_size) {
    (void)in_sizes; (void)n_in; (void)out_size;
    const int*   tokens = (const int*)  d_in[0];
    const float* wte    = (const float*)d_in[1];
    const float* wpe    = (const float*)d_in[2];
    const float* Wq     = (const float*)d_in[3];
    const float* Wk     = (const float*)d_in[4];
    const float* Wv     = (const float*)d_in[5];
    const float* Wo     = (const float*)d_in[6];
    const float* bo     = (const float*)d_in[7];
    const float* ln1_s  = (const float*)d_in[8];
    const float* ln1_b  = (const float*)d_in[9];
    const float* W1     = (const float*)d_in[10];
    const float* b1     = (const float*)d_in[11];
    const float* W2     = (const float*)d_in[12];
    const float* b2     = (const float*)d_in[13];
    const float* ln2_s  = (const float*)d_in[14];
    const float* ln2_b  = (const float*)d_in[15];
    const float* lnf_s  = (const float*)d_in[16];
    const float* lnf_b  = (const float*)d_in[17];
    float* out = (float*)d_out;

    float *x, *qkv;
    __half *hh, *atth, *m1h, *wqkvT, *woT, *w1T, *w2T, *wteh;
    cudaGetSymbolAddress((void**)&x,     g_x);
    cudaGetSymbolAddress((void**)&hh,    g_hh);
    cudaGetSymbolAddress((void**)&qkv,   g_qkv);
    cudaGetSymbolAddress((void**)&atth,  g_atth);
    cudaGetSymbolAddress((void**)&m1h,   g_m1h);
    cudaGetSymbolAddress((void**)&wqkvT, g_wqkvT);
    cudaGetSymbolAddress((void**)&woT,   g_woT);
    cudaGetSymbolAddress((void**)&w1T,   g_w1T);
    cudaGetSymbolAddress((void**)&w2T,   g_w2T);
    cudaGetSymbolAddress((void**)&wteh,  g_wteh);

    cudaFuncSetAttribute(attn_kernel,
                         cudaFuncAttributeMaxDynamicSharedMemorySize, ATTN_SMEM);
    cudaFuncSetAttribute(hgemm_k<0, false>,
                         cudaFuncAttributeMaxDynamicSharedMemorySize, SM_H128);
    cudaFuncSetAttribute(hgemm_k<3, true>,
                         cudaFuncAttributeMaxDynamicSharedMemorySize, SM_H128);
    cudaFuncSetAttribute(hgemm64_k<5>,
                         cudaFuncAttributeMaxDynamicSharedMemorySize, SM_H64);
    cudaFuncSetAttribute(logits_h_k,
                         cudaFuncAttributeMaxDynamicSharedMemorySize, SM_LOGH);

    // ---- per-launch weight transpose+convert to fp16 [N][K] ----
    {
        const dim3 trb(32, 8);
        const size_t sE = (size_t)E_SZ * E_SZ;
        const size_t sQ = (size_t)QKV_LD * E_SZ;
        const size_t sF = (size_t)E_SZ * FF;
        // Wq|Wk|Wv -> wqkvT [2304][768]
        tr_half_kernel<<<dim3(24, 24, L_SZ), trb>>>(Wq, wqkvT,              E_SZ, E_SZ, sE, sQ);
        tr_half_kernel<<<dim3(24, 24, L_SZ), trb>>>(Wk, wqkvT + sE,         E_SZ, E_SZ, sE, sQ);
        tr_half_kernel<<<dim3(24, 24, L_SZ), trb>>>(Wv, wqkvT + 2 * sE,     E_SZ, E_SZ, sE, sQ);
        tr_half_kernel<<<dim3(24, 24, L_SZ), trb>>>(Wo, woT,                E_SZ, E_SZ, sE, sE);
        tr_half_kernel<<<dim3(96, 24, L_SZ), trb>>>(W1, w1T,                E_SZ, FF,   sF, sF);
        tr_half_kernel<<<dim3(24, 96, L_SZ), trb>>>(W2, w2T,                FF,   E_SZ, sF, sF);
        const int nV = V_SZ * E_SZ / 4;
        cvt_half_kernel<<<(nV + 255) / 256, 256>>>((const float4*)wte, (uint2*)wteh, nV);
    }

    embed_kernel<<<BT, 192>>>(tokens, wte, wpe, x);

    const dim3 gQKV(BT / 128, QKV_LD / 128);       // 16 x 18
    const dim3 gF(BT / 128, FF / 128);             // 16 x 24
    const dim3 gE64(BT / 64, E_SZ / 64);           // 32 x 12
    const dim3 gATT(T_SZ / 64, B_SZ * H_SZ);       // 16 x 24
    const dim3 gLOG(BT / 128, (V_SZ + 127) / 128); // 16 x 393

    for (int l = 0; l < L_SZ; l++) {
        const size_t wqOff = (size_t)l * QKV_LD * E_SZ;
        const size_t wOff  = (size_t)l * E_SZ * E_SZ;
        const size_t w1Off = (size_t)l * FF * E_SZ;
        const size_t vOff  = (size_t)l * E_SZ;
        const size_t fOff  = (size_t)l * FF;

        layernorm_kernel<<<BT, 256>>>(x, ln1_s + vOff, ln1_b + vOff, hh);
        hgemm_k<0, false><<<gQKV, 256, SM_H128>>>(hh, wqkvT + wqOff, nullptr, nullptr,
                                                  qkv, nullptr, QKV_LD, E_SZ);
        attn_kernel<<<gATT, 256, ATTN_SMEM>>>(qkv, atth);
        hgemm64_k<5><<<gE64, 128, SM_H64>>>(atth, woT + wOff, bo + vOff, x, x, E_SZ, E_SZ);
        layernorm_kernel<<<BT, 256>>>(x, ln2_s + vOff, ln2_b + vOff, hh);
        hgemm_k<3, true><<<gF, 256, SM_H128>>>(hh, w1T + w1Off, b1 + fOff, nullptr,
                                               nullptr, m1h, FF, E_SZ);
        hgemm64_k<5><<<gE64, 128, SM_H64>>>(m1h, w2T + w1Off, b2 + vOff, x, x, E_SZ, FF);
    }

    layernorm_kernel<<<BT, 256>>>(x, lnf_s, lnf_b, hh);
    logits_h_k<<<gLOG, 256, SM_LOGH>>>(hh, wteh, out, V_SZ, E_SZ);
}

// round 17
// speedup vs baseline: 2.2791x; 1.4636x over previous
#include <cuda_runtime.h>
#include <cuda_fp16.h>
#include <math.h>
#include <stdint.h>

// ---------------- Problem constants ----------------
#define V_SZ 50257
#define E_SZ 768
#define H_SZ 12
#define L_SZ 6
#define T_SZ 1024
#define B_SZ 2
#define D_SZ 64
#define BT   (B_SZ * T_SZ)      // 2048
#define FF   (4 * E_SZ)         // 3072
#define QKV_LD (3 * E_SZ)       // 2304

// ---------------- Scratch ----------------
__device__ float  g_x    [BT * E_SZ];
__device__ __half g_hh   [BT * E_SZ];
__device__ __half g_qkvh [BT * QKV_LD];
__device__ __half g_atth [BT * E_SZ];
__device__ __half g_m1h  [BT * FF];
__device__ __half g_wqkvT[L_SZ * QKV_LD * E_SZ];
__device__ __half g_woT  [L_SZ * E_SZ * E_SZ];
__device__ __half g_w1T  [L_SZ * FF * E_SZ];
__device__ __half g_w2T  [L_SZ * E_SZ * FF];
__device__ __half g_wteh [V_SZ * E_SZ];

// ---------------- converts ----------------
__global__ void cvt_half_kernel(const float4* __restrict__ src, uint2* __restrict__ dst, int n4) {
    int i = blockIdx.x * 256 + threadIdx.x;
    if (i >= n4) return;
    float4 v = src[i];
    __half2 h0 = __floats2half2_rn(v.x, v.y);
    __half2 h1 = __floats2half2_rn(v.z, v.w);
    uint2 u;
    u.x = *(unsigned*)&h0;
    u.y = *(unsigned*)&h1;
    dst[i] = u;
}

// transpose-convert: src [K][N] fp32 -> dst [N][K] half.  block 32x8, grid (N/32, K/32, L)
__global__ void tr_half_kernel(const float* __restrict__ src, __half* __restrict__ dst,
                               int K, int N, size_t srcLS, size_t dstLS) {
    __shared__ float tile[32][33];
    const float* s = src + blockIdx.z * srcLS;
    __half* d = dst + blockIdx.z * dstLS;
    int n0 = blockIdx.x * 32, k0 = blockIdx.y * 32;
    int tx = threadIdx.x, ty = threadIdx.y;
#pragma unroll
    for (int j = 0; j < 4; j++)
        tile[ty + j * 8][tx] = s[(size_t)(k0 + ty + j * 8) * N + n0 + tx];
    __syncthreads();
#pragma unroll
    for (int j = 0; j < 4; j++)
        d[(size_t)(n0 + ty + j * 8) * K + k0 + tx] = __float2half_rn(tile[tx][ty + j * 8]);
}

// ---------------- Embedding ----------------
__global__ void embed_kernel(const int* __restrict__ tok,
                             const float* __restrict__ wte,
                             const float* __restrict__ wpe,
                             float* __restrict__ x) {
    int row = blockIdx.x;
    int t   = row % T_SZ;
    int tk  = tok[row];
    int e   = threadIdx.x * 4;
    const float4 a = *(const float4*)(wte + (size_t)tk * E_SZ + e);
    const float4 b = *(const float4*)(wpe + (size_t)t  * E_SZ + e);
    float4 o;
    o.x = a.x + b.x; o.y = a.y + b.y; o.z = a.z + b.z; o.w = a.w + b.w;
    *(float4*)(x + (size_t)row * E_SZ + e) = o;
}

// ---------------- LayerNorm: fp32 in -> fp16 out ----------------
__global__ void layernorm_kernel(const float* __restrict__ x,
                                 const float* __restrict__ sc,
                                 const float* __restrict__ bi,
                                 __half* __restrict__ out) {
    int row = blockIdx.x;
    const float* xr = x + (size_t)row * E_SZ;
    float lv[3];
    float s = 0.f, sq = 0.f;
#pragma unroll
    for (int i = 0; i < 3; i++) {
        float t = xr[threadIdx.x + i * 256];
        lv[i] = t; s += t; sq += t * t;
    }
#pragma unroll
    for (int o = 16; o > 0; o >>= 1) {
        s  += __shfl_down_sync(0xffffffffu, s,  o);
        sq += __shfl_down_sync(0xffffffffu, sq, o);
    }
    __shared__ float sa[8], sb[8];
    int w = threadIdx.x >> 5, lane = threadIdx.x & 31;
    if (lane == 0) { sa[w] = s; sb[w] = sq; }
    __syncthreads();
    __shared__ float s_mu, s_rstd;
    if (threadIdx.x == 0) {
        float ts = 0.f, tq = 0.f;
#pragma unroll
        for (int i = 0; i < 8; i++) { ts += sa[i]; tq += sb[i]; }
        float mu  = ts * (1.0f / E_SZ);
        float var = tq * (1.0f / E_SZ) - mu * mu;
        s_mu = mu;
        s_rstd = rsqrtf(var + 1e-5f);
    }
    __syncthreads();
    float mu = s_mu, rstd = s_rstd;
#pragma unroll
    for (int i = 0; i < 3; i++) {
        int c = threadIdx.x + i * 256;
        out[(size_t)row * E_SZ + c] = __float2half_rn((lv[i] - mu) * rstd * sc[c] + bi[c]);
    }
}

// ---------------- cp.async helpers ----------------
__device__ __forceinline__ void cp16(unsigned sdst, const void* src, bool pred) {
    int sz = pred ? 16 : 0;
    asm volatile("cp.async.cg.shared.global [%0], [%1], 16, %2;\n"
                 :: "r"(sdst), "l"(src), "r"(sz));
}
__device__ __forceinline__ void cp_commit() {
    asm volatile("cp.async.commit_group;\n");
}
__device__ __forceinline__ void cp_wait1() {
    asm volatile("cp.async.wait_group 1;\n");
}

__device__ __forceinline__ float gelu_exact(float v) {
    return 0.5f * v * (1.0f + erff(v * 0.70710678118654752f));
}
__device__ __forceinline__ void mma_f16(float* d, const unsigned* a, const unsigned* b) {
    asm volatile(
        "mma.sync.aligned.m16n8k16.row.col.f32.f16.f16.f32 "
        "{%0,%1,%2,%3}, {%4,%5,%6,%7}, {%8,%9}, {%0,%1,%2,%3};"
        : "+f"(d[0]), "+f"(d[1]), "+f"(d[2]), "+f"(d[3])
        : "r"(a[0]), "r"(a[1]), "r"(a[2]), "r"(a[3]), "r"(b[0]), "r"(b[1]));
}

#define HROW 40

// ---------------- hgemm: BM=128, BN=128, BK=32, 256 thr ----------------
#define SM_H128 (3 * 2 * 128 * HROW * 2)            // 61440

template <int EPI, bool OUTH>
__global__ __launch_bounds__(256)
void hgemm_k(const __half* __restrict__ A, const __half* __restrict__ B,
             const float* __restrict__ bias, const float* __restrict__ resid,
             float* __restrict__ C, __half* __restrict__ Ch, int N, int K) {
    constexpr int BK  = 32;
    constexpr int ASZ = 128 * HROW;

    extern __shared__ __half smem_h[];
    __half* sA = smem_h;
    __half* sB = smem_h + 3 * ASZ;

    const int bm  = blockIdx.x * 128;
    const int bn  = blockIdx.y * 128;
    const int tid = threadIdx.x;
    const int lane = tid & 31;
    const int wid  = tid >> 5;
    const int wm   = (wid & 3) * 32;
    const int wn   = (wid >> 2) * 64;
    const int g    = lane >> 2;
    const int t    = lane & 3;

    float acc[2][8][4];
#pragma unroll
    for (int i = 0; i < 2; i++)
#pragma unroll
        for (int j = 0; j < 8; j++)
#pragma unroll
            for (int r = 0; r < 4; r++) acc[i][j][r] = 0.f;

    const unsigned sAaddr = (unsigned)__cvta_generic_to_shared(sA);
    const unsigned sBaddr = (unsigned)__cvta_generic_to_shared(sB);
    const int ntiles = K / BK;

    auto issue = [&](int st, int kt) {
#pragma unroll
        for (int i = 0; i < 4; i++) {
            int f   = tid + i * 256;
            int isB = f >> 9;
            int row = (f >> 2) & 127;
            int c   = (f & 3) * 8;
            const __half* src = (isB ? B + (size_t)(bn + row) * K
                                     : A + (size_t)(bm + row) * K) + kt * BK + c;
            unsigned dst = (isB ? sBaddr : sAaddr) + (st * ASZ + row * HROW + c) * 2;
            cp16(dst, src, true);
        }
    };

    issue(0, 0); cp_commit();
    issue(1, 1); cp_commit();

    for (int kt = 0; kt < ntiles; kt++) {
        cp_wait1();
        __syncthreads();
        const int cur = kt % 3;
        const __half* As = sA + cur * ASZ;
        const __half* Bs = sB + cur * ASZ;
#pragma unroll
        for (int ks = 0; ks < 2; ks++) {
            const int kk0 = ks * 16;
            unsigned af[2][4], bf[8][2];
#pragma unroll
            for (int i = 0; i < 2; i++) {
                const int mr = wm + i * 16 + g;
                af[i][0] = *(const unsigned*)&As[mr * HROW + kk0 + 2 * t];
                af[i][1] = *(const unsigned*)&As[(mr + 8) * HROW + kk0 + 2 * t];
                af[i][2] = *(const unsigned*)&As[mr * HROW + kk0 + 2 * t + 8];
                af[i][3] = *(const unsigned*)&As[(mr + 8) * HROW + kk0 + 2 * t + 8];
            }
#pragma unroll
            for (int j = 0; j < 8; j++) {
                const int nc = wn + j * 8 + g;
                bf[j][0] = *(const unsigned*)&Bs[nc * HROW + kk0 + 2 * t];
                bf[j][1] = *(const unsigned*)&Bs[nc * HROW + kk0 + 2 * t + 8];
            }
#pragma unroll
            for (int i = 0; i < 2; i++)
#pragma unroll
                for (int j = 0; j < 8; j++)
                    mma_f16(acc[i][j], af[i], bf[j]);
        }
        if (kt + 2 < ntiles) issue((kt + 2) % 3, kt + 2);
        cp_commit();
    }

#pragma unroll
    for (int i = 0; i < 2; i++) {
        const int r0 = bm + wm + i * 16 + g;
        const int r1 = r0 + 8;
#pragma unroll
        for (int j = 0; j < 8; j++) {
            const int c = bn + wn + j * 8 + 2 * t;
            float v00 = acc[i][j][0], v01 = acc[i][j][1];
            float v10 = acc[i][j][2], v11 = acc[i][j][3];
            if (EPI & 1) {
                float bb0 = bias[c], bb1 = bias[c + 1];
                v00 += bb0; v01 += bb1; v10 += bb0; v11 += bb1;
            }
            if (EPI & 2) {
                v00 = gelu_exact(v00); v01 = gelu_exact(v01);
                v10 = gelu_exact(v10); v11 = gelu_exact(v11);
            }
            if (EPI & 4) {
                const float* rp0 = resid + (size_t)r0 * N + c;
                const float* rp1 = resid + (size_t)r1 * N + c;
                v00 += rp0[0]; v01 += rp0[1];
                v10 += rp1[0]; v11 += rp1[1];
            }
            if (OUTH) {
                __half2 p0 = __floats2half2_rn(v00, v01);
                __half2 p1 = __floats2half2_rn(v10, v11);
                *(__half2*)(Ch + (size_t)r0 * N + c) = p0;
                *(__half2*)(Ch + (size_t)r1 * N + c) = p1;
            } else {
                float2 p0; p0.x = v00; p0.y = v01;
                float2 p1; p1.x = v10; p1.y = v11;
                *(float2*)(C + (size_t)r0 * N + c) = p0;
                *(float2*)(C + (size_t)r1 * N + c) = p1;
            }
        }
    }
}

// ---------------- hgemm64: BM=64, BN=64, BK=32, 128 thr ----------------
#define SM_H64 (3 * 2 * 64 * HROW * 2)              // 30720

template <int EPI>
__global__ __launch_bounds__(128)
void hgemm64_k(const __half* __restrict__ A, const __half* __restrict__ B,
               const float* __restrict__ bias, const float* __restrict__ resid,
               float* __restrict__ C, int N, int K) {
    constexpr int BK  = 32;
    constexpr int ASZ = 64 * HROW;

    extern __shared__ __half smem_h[];
    __half* sA = smem_h;
    __half* sB = smem_h + 3 * ASZ;

    const int bm  = blockIdx.x * 64;
    const int bn  = blockIdx.y * 64;
    const int tid = threadIdx.x;
    const int lane = tid & 31;
    const int wid  = tid >> 5;
    const int wm   = (wid & 1) * 32;
    const int wn   = (wid >> 1) * 32;
    const int g    = lane >> 2;
    const int t    = lane & 3;

    float acc[2][4][4];
#pragma unroll
    for (int i = 0; i < 2; i++)
#pragma unroll
        for (int j = 0; j < 4; j++)
#pragma unroll
            for (int r = 0; r < 4; r++) acc[i][j][r] = 0.f;

    const unsigned sAaddr = (unsigned)__cvta_generic_to_shared(sA);
    const unsigned sBaddr = (unsigned)__cvta_generic_to_shared(sB);
    const int ntiles = K / BK;

    auto issue = [&](int st, int kt) {
#pragma unroll
        for (int i = 0; i < 4; i++) {
            int f   = tid + i * 128;
            int isB = f >> 8;
            int row = (f >> 2) & 63;
            int c   = (f & 3) * 8;
            const __half* src = (isB ? B + (size_t)(bn + row) * K
                                     : A + (size_t)(bm + row) * K) + kt * BK + c;
            unsigned dst = (isB ? sBaddr : sAaddr) + (st * ASZ + row * HROW + c) * 2;
            cp16(dst, src, true);
        }
    };

    issue(0, 0); cp_commit();
    issue(1, 1); cp_commit();

    for (int kt = 0; kt < ntiles; kt++) {
        cp_wait1();
        __syncthreads();
        const int cur = kt % 3;
        const __half* As = sA + cur * ASZ;
        const __half* Bs = sB + cur * ASZ;
#pragma unroll
        for (int ks = 0; ks < 2; ks++) {
            const int kk0 = ks * 16;
            unsigned af[2][4], bf[4][2];
#pragma unroll
            for (int i = 0; i < 2; i++) {
                const int mr = wm + i * 16 + g;
                af[i][0] = *(const unsigned*)&As[mr * HROW + kk0 + 2 * t];
                af[i][1] = *(const unsigned*)&As[(mr + 8) * HROW + kk0 + 2 * t];
                af[i][2] = *(const unsigned*)&As[mr * HROW + kk0 + 2 * t + 8];
                af[i][3] = *(const unsigned*)&As[(mr + 8) * HROW + kk0 + 2 * t + 8];
            }
#pragma unroll
            for (int j = 0; j < 4; j++) {
                const int nc = wn + j * 8 + g;
                bf[j][0] = *(const unsigned*)&Bs[nc * HROW + kk0 + 2 * t];
                bf[j][1] = *(const unsigned*)&Bs[nc * HROW + kk0 + 2 * t + 8];
            }
#pragma unroll
            for (int i = 0; i < 2; i++)
#pragma unroll
                for (int j = 0; j < 4; j++)
                    mma_f16(acc[i][j], af[i], bf[j]);
        }
        if (kt + 2 < ntiles) issue((kt + 2) % 3, kt + 2);
        cp_commit();
    }

#pragma unroll
    for (int i = 0; i < 2; i++) {
        const int r0 = bm + wm + i * 16 + g;
        const int r1 = r0 + 8;
#pragma unroll
        for (int j = 0; j < 4; j++) {
            const int c = bn + wn + j * 8 + 2 * t;
            float v00 = acc[i][j][0], v01 = acc[i][j][1];
            float v10 = acc[i][j][2], v11 = acc[i][j][3];
            if (EPI & 1) {
                float bb0 = bias[c], bb1 = bias[c + 1];
                v00 += bb0; v01 += bb1; v10 += bb0; v11 += bb1;
            }
            if (EPI & 2) {
                v00 = gelu_exact(v00); v01 = gelu_exact(v01);
                v10 = gelu_exact(v10); v11 = gelu_exact(v11);
            }
            if (EPI & 4) {
                const float* rp0 = resid + (size_t)r0 * N + c;
                const float* rp1 = resid + (size_t)r1 * N + c;
                v00 += rp0[0]; v01 += rp0[1];
                v10 += rp1[0]; v11 += rp1[1];
            }
            float2 p0; p0.x = v00; p0.y = v01;
            float2 p1; p1.x = v10; p1.y = v11;
            *(float2*)(C + (size_t)r0 * N + c) = p0;
            *(float2*)(C + (size_t)r1 * N + c) = p1;
        }
    }
}

// ---------------- fp16 logits GEMM ----------------
#define SM_LOGH (3 * 2 * 128 * HROW * 2)            // 61440

__global__ __launch_bounds__(256)
void logits_h_k(const __half* __restrict__ A, const __half* __restrict__ Bm,
                float* __restrict__ C, int N, int K) {
    constexpr int BK  = 32;
    constexpr int ASZ = 128 * HROW;

    extern __shared__ __half smem_h[];
    __half* sA = smem_h;
    __half* sB = smem_h + 3 * ASZ;

    const int bm  = blockIdx.x * 128;
    const int bn  = blockIdx.y * 128;
    const int tid = threadIdx.x;
    const int lane = tid & 31;
    const int wid  = tid >> 5;
    const int wm   = (wid & 3) * 32;
    const int wn   = (wid >> 2) * 64;
    const int g    = lane >> 2;
    const int t    = lane & 3;

    float acc[2][8][4];
#pragma unroll
    for (int i = 0; i < 2; i++)
#pragma unroll
        for (int j = 0; j < 8; j++)
#pragma unroll
            for (int r = 0; r < 4; r++) acc[i][j][r] = 0.f;

    const unsigned sAaddr = (unsigned)__cvta_generic_to_shared(sA);
    const unsigned sBaddr = (unsigned)__cvta_generic_to_shared(sB);
    const int ntiles = K / BK;

    auto issue = [&](int st, int kt) {
#pragma unroll
        for (int i = 0; i < 4; i++) {
            int f   = tid + i * 256;
            int isB = f >> 9;
            int row = (f >> 2) & 127;
            int c   = (f & 3) * 8;
            const __half* src;
            bool pred = true;
            if (isB) {
                int gn = bn + row;
                if (gn >= N) { gn = 0; pred = false; }
                src = Bm + (size_t)gn * K + kt * BK + c;
            } else {
                src = A + (size_t)(bm + row) * K + kt * BK + c;
            }
            unsigned dst = (isB ? sBaddr : sAaddr) + (st * ASZ + row * HROW + c) * 2;
            cp16(dst, src, pred);
        }
    };

    issue(0, 0); cp_commit();
    issue(1, 1); cp_commit();

    for (int kt = 0; kt < ntiles; kt++) {
        cp_wait1();
        __syncthreads();
        const int cur = kt % 3;
        const __half* As = sA + cur * ASZ;
        const __half* Bs = sB + cur * ASZ;
#pragma unroll
        for (int ks = 0; ks < 2; ks++) {
            const int kk0 = ks * 16;
            unsigned af[2][4], bf[8][2];
#pragma unroll
            for (int i = 0; i < 2; i++) {
                const int mr = wm + i * 16 + g;
                af[i][0] = *(const unsigned*)&As[mr * HROW + kk0 + 2 * t];
                af[i][1] = *(const unsigned*)&As[(mr + 8) * HROW + kk0 + 2 * t];
                af[i][2] = *(const unsigned*)&As[mr * HROW + kk0 + 2 * t + 8];
                af[i][3] = *(const unsigned*)&As[(mr + 8) * HROW + kk0 + 2 * t + 8];
            }
#pragma unroll
            for (int j = 0; j < 8; j++) {
                const int nc = wn + j * 8 + g;
                bf[j][0] = *(const unsigned*)&Bs[nc * HROW + kk0 + 2 * t];
                bf[j][1] = *(const unsigned*)&Bs[nc * HROW + kk0 + 2 * t + 8];
            }
#pragma unroll
            for (int i = 0; i < 2; i++)
#pragma unroll
                for (int j = 0; j < 8; j++)
                    mma_f16(acc[i][j], af[i], bf[j]);
        }
        if (kt + 2 < ntiles) issue((kt + 2) % 3, kt + 2);
        cp_commit();
    }

#pragma unroll
    for (int i = 0; i < 2; i++) {
        const int r0 = bm + wm + i * 16 + g;
        const int r1 = r0 + 8;
        float* cp0 = C + (size_t)r0 * N;
        float* cp1 = C + (size_t)r1 * N;
#pragma unroll
        for (int j = 0; j < 8; j++) {
            const int c = bn + wn + j * 8 + 2 * t;
            if (c < N)     { cp0[c]     = acc[i][j][0]; cp1[c]     = acc[i][j][2]; }
            if (c + 1 < N) { cp0[c + 1] = acc[i][j][1]; cp1[c + 1] = acc[i][j][3]; }
        }
    }
}

// ---------------- fp16 tensor-core flash attention ----------------
// 128 threads = 4 warps; warp w owns q rows [16w,16w+16) of a 64-q tile.
// S frags in registers; softmax fp32 via quad shuffles; P -> A-frags in-register.
#define ATTNH_SMEM (3 * 64 * 72 * 2)   // Qs,Ks,Vt = 27648 B

__global__ __launch_bounds__(128)
void attn_h_kernel(const __half* __restrict__ qkv, __half* __restrict__ o) {
    extern __shared__ __half smh[];
    __half* Qs = smh;                // [q][72]
    __half* Ks = smh + 64 * 72;      // [k][72]
    __half* Vt = smh + 2 * 64 * 72;  // [d][72] (V transposed)

    const int bh  = blockIdx.y;
    const int b   = bh / H_SZ, h = bh % H_SZ;
    const int q0  = blockIdx.x * 64;
    const int tid = threadIdx.x;
    const int lane = tid & 31;
    const int w    = tid >> 5;
    const int g    = lane >> 2;
    const int t    = lane & 3;

    const __half* qb = qkv + h * D_SZ;
    const __half* kb = qkv + E_SZ + h * D_SZ;
    const __half* vb = qkv + 2 * E_SZ + h * D_SZ;

    // Q tile, pre-scaled by 1/8 (exact in fp16)
    const __half2 qsc = __floats2half2_rn(0.125f, 0.125f);
#pragma unroll
    for (int i = 0; i < 8; i++) {
        int f  = tid + i * 128;
        int qq = f >> 4, d4 = (f & 15) * 4;
        uint2 u = *(const uint2*)(qb + (size_t)(b * T_SZ + q0 + qq) * QKV_LD + d4);
        __half2 h0 = __hmul2(*(__half2*)&u.x, qsc);
        __half2 h1 = __hmul2(*(__half2*)&u.y, qsc);
        u.x = *(unsigned*)&h0; u.y = *(unsigned*)&h1;
        *(uint2*)(Qs + qq * 72 + d4) = u;
    }

    float m0 = -1e30f, m1 = -1e30f, l0 = 0.f, l1 = 0.f;
    float oacc[8][4];
#pragma unroll
    for (int j = 0; j < 8; j++)
#pragma unroll
        for (int r = 0; r < 4; r++) oacc[j][r] = 0.f;

    const int qr = 16 * w + g;       // local q row (thread's row0)

    for (int kt = 0; kt <= q0; kt += 64) {
        // K tile [k][d]
#pragma unroll
        for (int i = 0; i < 8; i++) {
            int f  = tid + i * 128;
            int kk = f >> 4, d4 = (f & 15) * 4;
            *(uint2*)(Ks + kk * 72 + d4) =
                *(const uint2*)(kb + (size_t)(b * T_SZ + kt + kk) * QKV_LD + d4);
        }
        // V tile transposed: Vt[d][kk]; d-strided writes keep conflicts ~2-way
#pragma unroll
        for (int i = 0; i < 8; i++) {
            int f  = tid + i * 128;
            int kk = f >> 4, db = f & 15;
            const __half* vr = vb + (size_t)(b * T_SZ + kt + kk) * QKV_LD;
#pragma unroll
            for (int ms = 0; ms < 4; ms++)
                Vt[(db + 16 * ms) * 72 + kk] = vr[db + 16 * ms];
        }
        __syncthreads();

        // ---- S = Q K^T (contract over d, 4 chunks of 16) ----
        float s[8][4];
#pragma unroll
        for (int j = 0; j < 8; j++)
#pragma unroll
            for (int r = 0; r < 4; r++) s[j][r] = 0.f;
#pragma unroll
        for (int dc = 0; dc < 4; dc++) {
            const int d0 = dc * 16;
            unsigned af[4];
            af[0] = *(const unsigned*)&Qs[qr * 72 + d0 + 2 * t];
            af[1] = *(const unsigned*)&Qs[(qr + 8) * 72 + d0 + 2 * t];
            af[2] = *(const unsigned*)&Qs[qr * 72 + d0 + 2 * t + 8];
            af[3] = *(const unsigned*)&Qs[(qr + 8) * 72 + d0 + 2 * t + 8];
#pragma unroll
            for (int j = 0; j < 8; j++) {
                unsigned bf[2];
                bf[0] = *(const unsigned*)&Ks[(8 * j + g) * 72 + d0 + 2 * t];
                bf[1] = *(const unsigned*)&Ks[(8 * j + g) * 72 + d0 + 2 * t + 8];
                mma_f16(s[j], af, bf);
            }
        }

        // ---- causal mask (last tile only) ----
        if (kt == q0) {
#pragma unroll
            for (int j = 0; j < 8; j++) {
                const int c0 = 8 * j + 2 * t;
                if (c0     > qr)     s[j][0] = -1e30f;
                if (c0 + 1 > qr)     s[j][1] = -1e30f;
                if (c0     > qr + 8) s[j][2] = -1e30f;
                if (c0 + 1 > qr + 8) s[j][3] = -1e30f;
            }
        }

        // ---- online softmax (rows qr, qr+8; quad reductions) ----
        float mx0 = -1e30f, mx1 = -1e30f;
#pragma unroll
        for (int j = 0; j < 8; j++) {
            mx0 = fmaxf(mx0, fmaxf(s[j][0], s[j][1]));
            mx1 = fmaxf(mx1, fmaxf(s[j][2], s[j][3]));
        }
        mx0 = fmaxf(mx0, __shfl_xor_sync(0xffffffffu, mx0, 1));
        mx0 = fmaxf(mx0, __shfl_xor_sync(0xffffffffu, mx0, 2));
        mx1 = fmaxf(mx1, __shfl_xor_sync(0xffffffffu, mx1, 1));
        mx1 = fmaxf(mx1, __shfl_xor_sync(0xffffffffu, mx1, 2));
        const float mn0 = fmaxf(m0, mx0), mn1 = fmaxf(m1, mx1);
        const float cf0 = __expf(m0 - mn0), cf1 = __expf(m1 - mn1);
        m0 = mn0; m1 = mn1;
        float ps0 = 0.f, ps1 = 0.f;
#pragma unroll
        for (int j = 0; j < 8; j++) {
            s[j][0] = __expf(s[j][0] - mn0); s[j][1] = __expf(s[j][1] - mn0);
            s[j][2] = __expf(s[j][2] - mn1); s[j][3] = __expf(s[j][3] - mn1);
            ps0 += s[j][0] + s[j][1];
            ps1 += s[j][2] + s[j][3];
        }
        ps0 += __shfl_xor_sync(0xffffffffu, ps0, 1);
        ps0 += __shfl_xor_sync(0xffffffffu, ps0, 2);
        ps1 += __shfl_xor_sync(0xffffffffu, ps1, 1);
        ps1 += __shfl_xor_sync(0xffffffffu, ps1, 2);
        l0 = l0 * cf0 + ps0;
        l1 = l1 * cf1 + ps1;
#pragma unroll
        for (int j = 0; j < 8; j++) {
            oacc[j][0] *= cf0; oacc[j][1] *= cf0;
            oacc[j][2] *= cf1; oacc[j][3] *= cf1;
        }

        // ---- O += P V  (P C-frags -> A-frags in-register) ----
#pragma unroll
        for (int kc = 0; kc < 4; kc++) {
            unsigned pa[4];
            __half2 p;
            p = __floats2half2_rn(s[2*kc][0],     s[2*kc][1]);     pa[0] = *(unsigned*)&p;
            p = __floats2half2_rn(s[2*kc][2],     s[2*kc][3]);     pa[1] = *(unsigned*)&p;
            p = __floats2half2_rn(s[2*kc + 1][0], s[2*kc + 1][1]); pa[2] = *(unsigned*)&p;
            p = __floats2half2_rn(s[2*kc + 1][2], s[2*kc + 1][3]); pa[3] = *(unsigned*)&p;
#pragma unroll
            for (int j = 0; j < 8; j++) {
                unsigned bf[2];
                bf[0] = *(const unsigned*)&Vt[(8 * j + g) * 72 + kc * 16 + 2 * t];
                bf[1] = *(const unsigned*)&Vt[(8 * j + g) * 72 + kc * 16 + 2 * t + 8];
                mma_f16(oacc[j], pa, bf);
            }
        }
        __syncthreads();
    }

    // ---- epilogue: half output ----
    const float inv0 = 1.f / l0, inv1 = 1.f / l1;
    __half* op0 = o + (size_t)(b * T_SZ + q0 + qr) * E_SZ + h * D_SZ;
    __half* op1 = op0 + (size_t)8 * E_SZ;
#pragma unroll
    for (int j = 0; j < 8; j++) {
        __half2 a = __floats2half2_rn(oacc[j][0] * inv0, oacc[j][1] * inv0);
        __half2 c = __floats2half2_rn(oacc[j][2] * inv1, oacc[j][3] * inv1);
        *(__half2*)(op0 + 8 * j + 2 * t) = a;
        *(__half2*)(op1 + 8 * j + 2 * t) = c;
    }
}

// ---------------- Host orchestration ----------------
extern "C" void kernel_launch(void* const* d_in, const int* in_sizes, int n_in,
                              void* d_out, int out_size) {
    (void)in_sizes; (void)n_in; (void)out_size;
    const int*   tokens = (const int*)  d_in[0];
    const float* wte    = (const float*)d_in[1];
    const float* wpe    = (const float*)d_in[2];
    const float* Wq     = (const float*)d_in[3];
    const float* Wk     = (const float*)d_in[4];
    const float* Wv     = (const float*)d_in[5];
    const float* Wo     = (const float*)d_in[6];
    const float* bo     = (const float*)d_in[7];
    const float* ln1_s  = (const float*)d_in[8];
    const float* ln1_b  = (const float*)d_in[9];
    const float* W1     = (const float*)d_in[10];
    const float* b1     = (const float*)d_in[11];
    const float* W2     = (const float*)d_in[12];
    const float* b2     = (const float*)d_in[13];
    const float* ln2_s  = (const float*)d_in[14];
    const float* ln2_b  = (const float*)d_in[15];
    const float* lnf_s  = (const float*)d_in[16];
    const float* lnf_b  = (const float*)d_in[17];
    float* out = (float*)d_out;

    float *x;
    __half *hh, *qkvh, *atth, *m1h, *wqkvT, *woT, *w1T, *w2T, *wteh;
    cudaGetSymbolAddress((void**)&x,     g_x);
    cudaGetSymbolAddress((void**)&hh,    g_hh);
    cudaGetSymbolAddress((void**)&qkvh,  g_qkvh);
    cudaGetSymbolAddress((void**)&atth,  g_atth);
    cudaGetSymbolAddress((void**)&m1h,   g_m1h);
    cudaGetSymbolAddress((void**)&wqkvT, g_wqkvT);
    cudaGetSymbolAddress((void**)&woT,   g_woT);
    cudaGetSymbolAddress((void**)&w1T,   g_w1T);
    cudaGetSymbolAddress((void**)&w2T,   g_w2T);
    cudaGetSymbolAddress((void**)&wteh,  g_wteh);

    cudaFuncSetAttribute(attn_h_kernel,
                         cudaFuncAttributeMaxDynamicSharedMemorySize, ATTNH_SMEM);
    cudaFuncSetAttribute(hgemm_k<0, true>,
                         cudaFuncAttributeMaxDynamicSharedMemorySize, SM_H128);
    cudaFuncSetAttribute(hgemm_k<3, true>,
                         cudaFuncAttributeMaxDynamicSharedMemorySize, SM_H128);
    cudaFuncSetAttribute(hgemm64_k<5>,
                         cudaFuncAttributeMaxDynamicSharedMemorySize, SM_H64);
    cudaFuncSetAttribute(logits_h_k,
                         cudaFuncAttributeMaxDynamicSharedMemorySize, SM_LOGH);

    // ---- per-launch weight transpose+convert to fp16 [N][K] ----
    {
        const dim3 trb(32, 8);
        const size_t sE = (size_t)E_SZ * E_SZ;
        const size_t sQ = (size_t)QKV_LD * E_SZ;
        const size_t sF = (size_t)E_SZ * FF;
        tr_half_kernel<<<dim3(24, 24, L_SZ), trb>>>(Wq, wqkvT,          E_SZ, E_SZ, sE, sQ);
        tr_half_kernel<<<dim3(24, 24, L_SZ), trb>>>(Wk, wqkvT + sE,     E_SZ, E_SZ, sE, sQ);
        tr_half_kernel<<<dim3(24, 24, L_SZ), trb>>>(Wv, wqkvT + 2 * sE, E_SZ, E_SZ, sE, sQ);
        tr_half_kernel<<<dim3(24, 24, L_SZ), trb>>>(Wo, woT,            E_SZ, E_SZ, sE, sE);
        tr_half_kernel<<<dim3(96, 24, L_SZ), trb>>>(W1, w1T,            E_SZ, FF,   sF, sF);
        tr_half_kernel<<<dim3(24, 96, L_SZ), trb>>>(W2, w2T,            FF,   E_SZ, sF, sF);
        const int nV = V_SZ * E_SZ / 4;
        cvt_half_kernel<<<(nV + 255) / 256, 256>>>((const float4*)wte, (uint2*)wteh, nV);
    }

    embed_kernel<<<BT, 192>>>(tokens, wte, wpe, x);

    const dim3 gQKV(BT / 128, QKV_LD / 128);       // 16 x 18
    const dim3 gF(BT / 128, FF / 128);             // 16 x 24
    const dim3 gE64(BT / 64, E_SZ / 64);           // 32 x 12
    const dim3 gATT(T_SZ / 64, B_SZ * H_SZ);       // 16 x 24
    const dim3 gLOG(BT / 128, (V_SZ + 127) / 128); // 16 x 393

    for (int l = 0; l < L_SZ; l++) {
        const size_t wqOff = (size_t)l * QKV_LD * E_SZ;
        const size_t wOff  = (size_t)l * E_SZ * E_SZ;
        const size_t w1Off = (size_t)l * FF * E_SZ;
        const size_t vOff  = (size_t)l * E_SZ;
        const size_t fOff  = (size_t)l * FF;

        layernorm_kernel<<<BT, 256>>>(x, ln1_s + vOff, ln1_b + vOff, hh);
        hgemm_k<0, true><<<gQKV, 256, SM_H128>>>(hh, wqkvT + wqOff, nullptr, nullptr,
                                                 nullptr, qkvh, QKV_LD, E_SZ);
        attn_h_kernel<<<gATT, 128, ATTNH_SMEM>>>(qkvh, atth);
        hgemm64_k<5><<<gE64, 128, SM_H64>>>(atth, woT + wOff, bo + vOff, x, x, E_SZ, E_SZ);
        layernorm_kernel<<<BT, 256>>>(x, ln2_s + vOff, ln2_b + vOff, hh);
        hgemm_k<3, true><<<gF, 256, SM_H128>>>(hh, w1T + w1Off, b1 + fOff, nullptr,
                                               nullptr, m1h, FF, E_SZ);
        hgemm64_k<5><<<gE64, 128, SM_H64>>>(m1h, w2T + w1Off, b2 + vOff, x, x, E_SZ, FF);
    }

    layernorm_kernel<<<BT, 256>>>(x, lnf_s, lnf_b, hh);
    logits_h_k<<<gLOG, 256, SM_LOGH>>>(hh, wteh, out, V_SZ, E_SZ);
}